// round 1
// baseline (speedup 1.0000x reference)
#include <cuda_runtime.h>
#include <math.h>

#define N_NODES 50000
#define N_EDGES 800000
#define DIM_IN  256
#define DIM_HID 128
#define DIM_OUT 64

// ---------------- device scratch (no allocation allowed) ----------------
__device__ float g_dinv[N_NODES];
__device__ float g_h1[N_NODES * DIM_HID];
__device__ float g_agg1[N_NODES * DIM_HID];
__device__ float g_h2[N_NODES * DIM_OUT];
__device__ float g_agg2[N_NODES * DIM_OUT];
__device__ int   g_src[N_EDGES];
__device__ int   g_dst[N_EDGES];
__device__ int   g_is64;

// ---------------- edge dtype detection + normalization ----------------
// jnp.int64 under default JAX config silently becomes int32. True int64
// indices are all < 50000, so any int64-interpreted value >= N_NODES (or < 0)
// means the buffer is really int32 pairs packed into 8 bytes.
__global__ void detect_edge_dtype_kernel(const void* edge) {
    if (threadIdx.x == 0 && blockIdx.x == 0) {
        const long long* e64 = (const long long*)edge;
        int ok = 1;
        for (int i = 0; i < 16; i++) {
            long long v = e64[i];
            if (v < 0 || v >= (long long)N_NODES) { ok = 0; break; }
        }
        g_is64 = ok;
    }
}

__global__ void convert_edges_kernel(const void* edge) {
    int i = blockIdx.x * blockDim.x + threadIdx.x;
    if (i >= 2 * N_EDGES) return;
    int is64 = g_is64;
    int v;
    if (is64) v = (int)((const long long*)edge)[i];
    else      v = ((const int*)edge)[i];
    if (i < N_EDGES) g_src[i] = v;
    else             g_dst[i - N_EDGES] = v;
}

// ---------------- degree / normalization ----------------
__global__ void deg_init_kernel(float* deg) {
    int i = blockIdx.x * blockDim.x + threadIdx.x;
    if (i < N_NODES) deg[i] = 1.0f;   // self loop
}

__global__ void deg_count_kernel(float* deg) {
    int i = blockIdx.x * blockDim.x + threadIdx.x;
    if (i < N_EDGES) atomicAdd(&deg[g_dst[i]], 1.0f);
}

__global__ void deg_rsqrt_kernel(float* deg) {
    int i = blockIdx.x * blockDim.x + threadIdx.x;
    if (i < N_NODES) deg[i] = rsqrtf(deg[i]);
}

// ---------------- tiled fp32 GEMM: C[M,N] = A[M,K] @ B[K,N] ----------------
// BM=64, BN=64, BK=16, TM=4, TN=4, 256 threads.
template<int BM, int BN, int BK, int TM, int TN>
__global__ void gemm_kernel(const float* __restrict__ A,
                            const float* __restrict__ B,
                            float* __restrict__ C,
                            int M, int K, int N) {
    __shared__ float As[BK][BM];
    __shared__ float Bs[BK][BN];

    const int block_row = blockIdx.y * BM;
    const int block_col = blockIdx.x * BN;
    const int tid  = threadIdx.x;                 // 256 threads
    const int tcol = (tid % (BN / TN)) * TN;      // 16 col-groups
    const int trow = (tid / (BN / TN)) * TM;      // 16 row-groups

    float acc[TM][TN];
    #pragma unroll
    for (int i = 0; i < TM; i++)
        #pragma unroll
        for (int j = 0; j < TN; j++) acc[i][j] = 0.0f;

    for (int k0 = 0; k0 < K; k0 += BK) {
        // load A tile (BM x BK)
        #pragma unroll
        for (int i = tid; i < BM * BK; i += 256) {
            int r = i / BK, c = i % BK;
            int gr = block_row + r;
            As[c][r] = (gr < M) ? A[(size_t)gr * K + k0 + c] : 0.0f;
        }
        // load B tile (BK x BN)
        #pragma unroll
        for (int i = tid; i < BK * BN; i += 256) {
            int r = i / BN, c = i % BN;
            Bs[r][c] = B[(size_t)(k0 + r) * N + block_col + c];
        }
        __syncthreads();

        #pragma unroll
        for (int kk = 0; kk < BK; kk++) {
            float a[TM], b[TN];
            #pragma unroll
            for (int i = 0; i < TM; i++) a[i] = As[kk][trow + i];
            #pragma unroll
            for (int j = 0; j < TN; j++) b[j] = Bs[kk][tcol + j];
            #pragma unroll
            for (int i = 0; i < TM; i++)
                #pragma unroll
                for (int j = 0; j < TN; j++)
                    acc[i][j] += a[i] * b[j];
        }
        __syncthreads();
    }

    #pragma unroll
    for (int i = 0; i < TM; i++) {
        int r = block_row + trow + i;
        if (r < M) {
            #pragma unroll
            for (int j = 0; j < TN; j++)
                C[(size_t)r * N + block_col + tcol + j] = acc[i][j];
        }
    }
}

// ---------------- self-loop init: agg[i] = h[i] * dinv[node]^2 ----------------
__global__ void selfloop_kernel(const float* __restrict__ h,
                                float* __restrict__ agg,
                                const float* __restrict__ dinv,
                                int total, int C) {
    int i = blockIdx.x * blockDim.x + threadIdx.x;
    if (i < total) {
        int node = i / C;
        float di = dinv[node];
        agg[i] = h[i] * di * di;
    }
}

// ---------------- edge scatter: agg[dst] += h[src] * dinv[src]*dinv[dst] ----------------
// one warp per edge, C/32 channels per lane, coalesced
template<int C>
__global__ void scatter_kernel(const float* __restrict__ h,
                               float* __restrict__ agg,
                               const float* __restrict__ dinv) {
    int gw   = (blockIdx.x * blockDim.x + threadIdx.x) >> 5;
    int lane = threadIdx.x & 31;
    if (gw >= N_EDGES) return;
    int s = g_src[gw];
    int d = g_dst[gw];
    float norm = dinv[s] * dinv[d];
    const float* hs = h + (size_t)s * C;
    float* ad = agg + (size_t)d * C;
    #pragma unroll
    for (int k = 0; k < C / 32; k++) {
        int c = k * 32 + lane;
        atomicAdd(&ad[c], hs[c] * norm);
    }
}

// ---------------- bias (+relu) + sigmoid gate, one warp per node ----------------
template<int C, bool RELU>
__global__ void gate_kernel(const float* __restrict__ agg,
                            const float* __restrict__ bias,
                            const float* __restrict__ aw,
                            const float* __restrict__ ab,
                            float* __restrict__ out) {
    int gw   = (blockIdx.x * blockDim.x + threadIdx.x) >> 5;
    int lane = threadIdx.x & 31;
    if (gw >= N_NODES) return;

    float v[C / 32];
    float dot = 0.0f;
    #pragma unroll
    for (int k = 0; k < C / 32; k++) {
        int c = k * 32 + lane;
        float x = agg[(size_t)gw * C + c] + bias[c];
        if (RELU) x = fmaxf(x, 0.0f);
        v[k] = x;
        dot += x * aw[c];
    }
    #pragma unroll
    for (int off = 16; off > 0; off >>= 1)
        dot += __shfl_xor_sync(0xffffffffu, dot, off);

    float g = 1.0f / (1.0f + expf(-(dot + ab[0])));
    #pragma unroll
    for (int k = 0; k < C / 32; k++)
        out[(size_t)gw * C + k * 32 + lane] = v[k] * g;
}

// ---------------- launch ----------------
extern "C" void kernel_launch(void* const* d_in, const int* in_sizes, int n_in,
                              void* d_out, int out_size) {
    const float* x   = (const float*)d_in[0];
    const void*  edge = d_in[1];
    const float* W1  = (const float*)d_in[2];
    const float* b1  = (const float*)d_in[3];
    const float* W2  = (const float*)d_in[4];
    const float* b2  = (const float*)d_in[5];
    const float* aw1 = (const float*)d_in[6];
    const float* ab1 = (const float*)d_in[7];
    const float* aw2 = (const float*)d_in[8];
    const float* ab2 = (const float*)d_in[9];
    float* out = (float*)d_out;

    float *dinv, *h1, *agg1, *h2, *agg2;
    cudaGetSymbolAddress((void**)&dinv, g_dinv);
    cudaGetSymbolAddress((void**)&h1,   g_h1);
    cudaGetSymbolAddress((void**)&agg1, g_agg1);
    cudaGetSymbolAddress((void**)&h2,   g_h2);
    cudaGetSymbolAddress((void**)&agg2, g_agg2);

    const int T = 256;

    // edge normalization (detect int32 vs int64, convert to int)
    detect_edge_dtype_kernel<<<1, 32>>>(edge);
    convert_edges_kernel<<<(2 * N_EDGES + T - 1) / T, T>>>(edge);

    // degree + rsqrt
    deg_init_kernel<<<(N_NODES + T - 1) / T, T>>>(dinv);
    deg_count_kernel<<<(N_EDGES + T - 1) / T, T>>>(dinv);
    deg_rsqrt_kernel<<<(N_NODES + T - 1) / T, T>>>(dinv);

    // ---- layer 1 ----
    {
        dim3 grid((DIM_HID + 63) / 64, (N_NODES + 63) / 64);
        gemm_kernel<64, 64, 16, 4, 4><<<grid, 256>>>(x, W1, h1, N_NODES, DIM_IN, DIM_HID);
    }
    selfloop_kernel<<<(N_NODES * DIM_HID + T - 1) / T, T>>>(h1, agg1, dinv, N_NODES * DIM_HID, DIM_HID);
    scatter_kernel<DIM_HID><<<(N_EDGES * 32 + T - 1) / T, T>>>(h1, agg1, dinv);
    // bias + relu + gate1 -> write back into h1 (input to layer 2)
    gate_kernel<DIM_HID, true><<<(N_NODES * 32 + T - 1) / T, T>>>(agg1, b1, aw1, ab1, h1);

    // ---- layer 2 ----
    {
        dim3 grid((DIM_OUT + 63) / 64, (N_NODES + 63) / 64);
        gemm_kernel<64, 64, 16, 4, 4><<<grid, 256>>>(h1, W2, h2, N_NODES, DIM_HID, DIM_OUT);
    }
    selfloop_kernel<<<(N_NODES * DIM_OUT + T - 1) / T, T>>>(h2, agg2, dinv, N_NODES * DIM_OUT, DIM_OUT);
    scatter_kernel<DIM_OUT><<<(N_EDGES * 32 + T - 1) / T, T>>>(h2, agg2, dinv);
    // bias (no relu) + gate2 -> final output
    gate_kernel<DIM_OUT, false><<<(N_NODES * 32 + T - 1) / T, T>>>(agg2, b2, aw2, ab2, out);
}

// round 2
// speedup vs baseline: 1.4578x; 1.4578x over previous
#include <cuda_runtime.h>
#include <math.h>

#define N_NODES 50000
#define N_EDGES 800000
#define DIM_IN  256
#define DIM_HID 128
#define DIM_OUT 64

// ---------------- device scratch (no allocation allowed) ----------------
__device__ float g_dinv[N_NODES];
__device__ float g_ht1[N_NODES * DIM_HID];   // h1 * dinv (then reused for y1)
__device__ float g_agg1[N_NODES * DIM_HID];
__device__ float g_ht2[N_NODES * DIM_OUT];   // h2 * dinv
__device__ float g_agg2[N_NODES * DIM_OUT];
__device__ int   g_src[N_EDGES];
__device__ int   g_dst[N_EDGES];
__device__ int   g_is64;

// ---------------- edge dtype detection ----------------
__global__ void detect_edge_dtype_kernel(const void* edge) {
    if (threadIdx.x == 0 && blockIdx.x == 0) {
        const long long* e64 = (const long long*)edge;
        int ok = 1;
        for (int i = 0; i < 16; i++) {
            long long v = e64[i];
            if (v < 0 || v >= (long long)N_NODES) { ok = 0; break; }
        }
        g_is64 = ok;
    }
}

// convert edges to int32 AND count in-degree (fused)
__global__ void convert_edges_kernel(const void* edge, float* deg) {
    int i = blockIdx.x * blockDim.x + threadIdx.x;
    if (i >= 2 * N_EDGES) return;
    int v;
    if (g_is64) v = (int)((const long long*)edge)[i];
    else        v = ((const int*)edge)[i];
    if (i < N_EDGES) g_src[i] = v;
    else {
        g_dst[i - N_EDGES] = v;
        atomicAdd(&deg[v], 1.0f);
    }
}

__global__ void deg_init_kernel(float* deg) {
    int i = blockIdx.x * blockDim.x + threadIdx.x;
    if (i < N_NODES) deg[i] = 1.0f;   // self loop
}

__global__ void deg_rsqrt_kernel(float* deg) {
    int i = blockIdx.x * blockDim.x + threadIdx.x;
    if (i < N_NODES) deg[i] = rsqrtf(deg[i]);
}

// ---------------- tiled fp32 GEMM with scaled dual-store epilogue ----------------
// Ht[r,:] = Agg[r,:] = (A @ B)[r,:] * dinv[r]
template<int BM, int BN, int BK, int TM, int TN>
__global__ __launch_bounds__((BM/TM)*(BN/TN))
void gemm_scaled_kernel(const float* __restrict__ A,
                        const float* __restrict__ B,
                        const float* __restrict__ dinv,
                        float* __restrict__ Ht,
                        float* __restrict__ Agg,
                        int M, int K, int N) {
    constexpr int THREADS = (BM/TM)*(BN/TN);
    __shared__ float As[BK][BM];
    __shared__ float Bs[BK][BN];

    const int block_row = blockIdx.y * BM;
    const int block_col = blockIdx.x * BN;
    const int tid  = threadIdx.x;
    const int tcol = (tid % (BN / TN)) * TN;
    const int trow = (tid / (BN / TN)) * TM;

    float acc[TM][TN];
    #pragma unroll
    for (int i = 0; i < TM; i++)
        #pragma unroll
        for (int j = 0; j < TN; j++) acc[i][j] = 0.0f;

    constexpr int A_F4 = BM * BK / 4;   // float4 elements in A tile
    constexpr int B_F4 = BK * BN / 4;

    for (int k0 = 0; k0 < K; k0 += BK) {
        // A tile: BM x BK, float4 along K, stored transposed into As
        #pragma unroll
        for (int l = 0; l < A_F4 / THREADS; l++) {
            int idx = tid + l * THREADS;
            int r  = idx / (BK / 4);
            int c4 = idx % (BK / 4);
            int gr = block_row + r;
            float4 v = make_float4(0.f, 0.f, 0.f, 0.f);
            if (gr < M)
                v = *(const float4*)&A[(size_t)gr * K + k0 + c4 * 4];
            As[c4 * 4 + 0][r] = v.x;
            As[c4 * 4 + 1][r] = v.y;
            As[c4 * 4 + 2][r] = v.z;
            As[c4 * 4 + 3][r] = v.w;
        }
        // B tile: BK x BN, float4 along N
        #pragma unroll
        for (int l = 0; l < B_F4 / THREADS; l++) {
            int idx = tid + l * THREADS;
            int r  = idx / (BN / 4);
            int c4 = idx % (BN / 4);
            float4 v = *(const float4*)&B[(size_t)(k0 + r) * N + block_col + c4 * 4];
            *(float4*)&Bs[r][c4 * 4] = v;
        }
        __syncthreads();

        #pragma unroll
        for (int kk = 0; kk < BK; kk++) {
            float a[TM], b[TN];
            #pragma unroll
            for (int i = 0; i < TM; i++) a[i] = As[kk][trow + i];
            #pragma unroll
            for (int j = 0; j < TN; j++) b[j] = Bs[kk][tcol + j];
            #pragma unroll
            for (int i = 0; i < TM; i++)
                #pragma unroll
                for (int j = 0; j < TN; j++)
                    acc[i][j] += a[i] * b[j];
        }
        __syncthreads();
    }

    #pragma unroll
    for (int i = 0; i < TM; i++) {
        int r = block_row + trow + i;
        if (r < M) {
            float di = dinv[r];
            #pragma unroll
            for (int j4 = 0; j4 < TN / 4; j4++) {
                float4 v;
                v.x = acc[i][j4 * 4 + 0] * di;
                v.y = acc[i][j4 * 4 + 1] * di;
                v.z = acc[i][j4 * 4 + 2] * di;
                v.w = acc[i][j4 * 4 + 3] * di;
                size_t off = (size_t)r * N + block_col + tcol + j4 * 4;
                *(float4*)&Ht[off]  = v;
                *(float4*)&Agg[off] = v;
            }
        }
    }
}

// ---------------- edge scatter: agg[dst] += ht[src] (vector atomics) ----------------
template<int C>
__global__ void scatter_kernel(const float* __restrict__ ht,
                               float* __restrict__ agg) {
    constexpr int CH4 = C / 4;
    int t = blockIdx.x * blockDim.x + threadIdx.x;
    int e = t / CH4;
    int j = t % CH4;
    if (e >= N_EDGES) return;
    int s = g_src[e];
    int d = g_dst[e];
    float4 v = ((const float4*)(ht + (size_t)s * C))[j];
    float4* p = (float4*)(agg + (size_t)d * C) + j;
    asm volatile("red.global.add.v4.f32 [%0], {%1, %2, %3, %4};"
                 :: "l"(p), "f"(v.x), "f"(v.y), "f"(v.z), "f"(v.w)
                 : "memory");
}

// ---------------- epilogue: z = [relu](agg*dinv + b); out = z * sigmoid(z@aw+ab) ----------------
template<int C, bool RELU>
__global__ void gate_kernel(const float* __restrict__ agg,
                            const float* __restrict__ dinv,
                            const float* __restrict__ bias,
                            const float* __restrict__ aw,
                            const float* __restrict__ ab,
                            float* __restrict__ out) {
    int gw   = (blockIdx.x * blockDim.x + threadIdx.x) >> 5;
    int lane = threadIdx.x & 31;
    if (gw >= N_NODES) return;

    float di = dinv[gw];
    float v[C / 32];
    float dot = 0.0f;
    #pragma unroll
    for (int k = 0; k < C / 32; k++) {
        int c = k * 32 + lane;
        float x = agg[(size_t)gw * C + c] * di + bias[c];
        if (RELU) x = fmaxf(x, 0.0f);
        v[k] = x;
        dot += x * aw[c];
    }
    #pragma unroll
    for (int off = 16; off > 0; off >>= 1)
        dot += __shfl_xor_sync(0xffffffffu, dot, off);

    float g = 1.0f / (1.0f + expf(-(dot + ab[0])));
    #pragma unroll
    for (int k = 0; k < C / 32; k++)
        out[(size_t)gw * C + k * 32 + lane] = v[k] * g;
}

// ---------------- launch ----------------
extern "C" void kernel_launch(void* const* d_in, const int* in_sizes, int n_in,
                              void* d_out, int out_size) {
    const float* x    = (const float*)d_in[0];
    const void*  edge = d_in[1];
    const float* W1  = (const float*)d_in[2];
    const float* b1  = (const float*)d_in[3];
    const float* W2  = (const float*)d_in[4];
    const float* b2  = (const float*)d_in[5];
    const float* aw1 = (const float*)d_in[6];
    const float* ab1 = (const float*)d_in[7];
    const float* aw2 = (const float*)d_in[8];
    const float* ab2 = (const float*)d_in[9];
    float* out = (float*)d_out;

    float *dinv, *ht1, *agg1, *ht2, *agg2;
    cudaGetSymbolAddress((void**)&dinv, g_dinv);
    cudaGetSymbolAddress((void**)&ht1,  g_ht1);
    cudaGetSymbolAddress((void**)&agg1, g_agg1);
    cudaGetSymbolAddress((void**)&ht2,  g_ht2);
    cudaGetSymbolAddress((void**)&agg2, g_agg2);

    const int T = 256;

    detect_edge_dtype_kernel<<<1, 32>>>(edge);
    deg_init_kernel<<<(N_NODES + T - 1) / T, T>>>(dinv);
    convert_edges_kernel<<<(2 * N_EDGES + T - 1) / T, T>>>(edge, dinv);
    deg_rsqrt_kernel<<<(N_NODES + T - 1) / T, T>>>(dinv);

    // ---- layer 1: ht1 = agg1 = (x@W1)*dinv ----
    {
        dim3 grid(DIM_HID / 128, (N_NODES + 127) / 128);
        gemm_scaled_kernel<128, 128, 16, 8, 8><<<grid, 256>>>(
            x, W1, dinv, ht1, agg1, N_NODES, DIM_IN, DIM_HID);
    }
    scatter_kernel<DIM_HID><<<(N_EDGES * (DIM_HID / 4) + T - 1) / T, T>>>(ht1, agg1);
    // y1 = relu(agg1*dinv + b1) * sigmoid(...) -> reuse ht1 buffer
    gate_kernel<DIM_HID, true><<<(N_NODES * 32 + T - 1) / T, T>>>(agg1, dinv, b1, aw1, ab1, ht1);

    // ---- layer 2: ht2 = agg2 = (y1@W2)*dinv ----
    {
        dim3 grid(DIM_OUT / 64, (N_NODES + 127) / 128);
        gemm_scaled_kernel<128, 64, 16, 8, 4><<<grid, 256>>>(
            ht1, W2, dinv, ht2, agg2, N_NODES, DIM_HID, DIM_OUT);
    }
    scatter_kernel<DIM_OUT><<<(N_EDGES * (DIM_OUT / 4) + T - 1) / T, T>>>(ht2, agg2);
    gate_kernel<DIM_OUT, false><<<(N_NODES * 32 + T - 1) / T, T>>>(agg2, dinv, b2, aw2, ab2, out);
}

// round 3
// speedup vs baseline: 1.8259x; 1.2525x over previous
#include <cuda_runtime.h>
#include <math.h>

#define N_NODES 50000
#define N_EDGES 800000
#define DIM_IN  256
#define DIM_HID 128
#define DIM_OUT 64

// ---------------- device scratch (no allocation allowed) ----------------
__device__ float g_dinv[N_NODES];
__device__ float g_ht1[N_NODES * DIM_HID];
__device__ float g_agg1[N_NODES * DIM_HID];
__device__ float g_ht2[N_NODES * DIM_OUT];
__device__ float g_agg2[N_NODES * DIM_OUT];
__device__ int   g_src[N_EDGES];
__device__ int   g_dst[N_EDGES];
__device__ int   g_is64;

// ---------------- edge dtype detection ----------------
__global__ void detect_edge_dtype_kernel(const void* edge) {
    if (threadIdx.x == 0 && blockIdx.x == 0) {
        const long long* e64 = (const long long*)edge;
        int ok = 1;
        for (int i = 0; i < 16; i++) {
            long long v = e64[i];
            if (v < 0 || v >= (long long)N_NODES) { ok = 0; break; }
        }
        g_is64 = ok;
    }
}

// convert edges to int32 AND count in-degree (fused)
__global__ void convert_edges_kernel(const void* edge, float* deg) {
    int i = blockIdx.x * blockDim.x + threadIdx.x;
    if (i >= 2 * N_EDGES) return;
    int v;
    if (g_is64) v = (int)((const long long*)edge)[i];
    else        v = ((const int*)edge)[i];
    if (i < N_EDGES) g_src[i] = v;
    else {
        g_dst[i - N_EDGES] = v;
        atomicAdd(&deg[v], 1.0f);
    }
}

__global__ void deg_init_kernel(float* deg) {
    int i = blockIdx.x * blockDim.x + threadIdx.x;
    if (i < N_NODES) deg[i] = 1.0f;   // self loop
}

__global__ void deg_rsqrt_kernel(float* deg) {
    int i = blockIdx.x * blockDim.x + threadIdx.x;
    if (i < N_NODES) deg[i] = rsqrtf(deg[i]);
}

// ---------------- tf32 helpers ----------------
__device__ __forceinline__ unsigned f2tf32(float f) {
    unsigned u;
    asm("cvt.rna.tf32.f32 %0, %1;" : "=r"(u) : "f"(f));
    return u;
}

// ---------------- tf32 tensor-core GEMM with scaled dual-store epilogue ----------------
// Ht[r,:] = Agg[r,:] = (A @ B)[r,:] * dinv[r]
// Block tile 128x64, BK=32, 8 warps in 4(M) x 2(N); warp tile 32x32 = 2x4 m16n8k8.
#define BM 128
#define BN 64
#define BK 32
#define AS_STRIDE 33
#define BS_STRIDE 68

__global__ __launch_bounds__(256)
void gemm_tf32_kernel(const float* __restrict__ A,
                      const float* __restrict__ B,
                      const float* __restrict__ dinv,
                      float* __restrict__ Ht,
                      float* __restrict__ Agg,
                      int M, int K, int N) {
    __shared__ unsigned As[BM * AS_STRIDE];   // [row][k], tf32 bits
    __shared__ unsigned Bs[BK * BS_STRIDE];   // [k][col], tf32 bits

    const int tid  = threadIdx.x;
    const int warp = tid >> 5;
    const int lane = tid & 31;
    const int wr = (warp & 3) * 32;   // warp row offset in block
    const int wc = (warp >> 2) * 32;  // warp col offset in block
    const int block_row = blockIdx.y * BM;
    const int block_col = blockIdx.x * BN;

    const int lq = lane >> 2;   // 0..7
    const int lr = lane & 3;    // 0..3

    float acc[2][4][4];
    #pragma unroll
    for (int mt = 0; mt < 2; mt++)
        #pragma unroll
        for (int nt = 0; nt < 4; nt++)
            #pragma unroll
            for (int i = 0; i < 4; i++) acc[mt][nt][i] = 0.0f;

    for (int k0 = 0; k0 < K; k0 += BK) {
        // A tile: 128 rows x 32 cols = 1024 float4, 4 per thread
        #pragma unroll
        for (int l = 0; l < 4; l++) {
            int idx = tid + l * 256;
            int r  = idx >> 3;         // /8
            int c4 = idx & 7;
            int gr = block_row + r;
            float4 v = make_float4(0.f, 0.f, 0.f, 0.f);
            if (gr < M)
                v = *(const float4*)&A[(size_t)gr * K + k0 + c4 * 4];
            unsigned* dst = &As[r * AS_STRIDE + c4 * 4];
            dst[0] = f2tf32(v.x); dst[1] = f2tf32(v.y);
            dst[2] = f2tf32(v.z); dst[3] = f2tf32(v.w);
        }
        // B tile: 32 rows x 64 cols = 512 float4, 2 per thread
        #pragma unroll
        for (int l = 0; l < 2; l++) {
            int idx = tid + l * 256;
            int r  = idx >> 4;         // /16
            int c4 = idx & 15;
            float4 v = *(const float4*)&B[(size_t)(k0 + r) * N + block_col + c4 * 4];
            unsigned* dst = &Bs[r * BS_STRIDE + c4 * 4];
            dst[0] = f2tf32(v.x); dst[1] = f2tf32(v.y);
            dst[2] = f2tf32(v.z); dst[3] = f2tf32(v.w);
        }
        __syncthreads();

        #pragma unroll
        for (int kk = 0; kk < BK; kk += 8) {
            unsigned a[2][4], b[4][2];
            #pragma unroll
            for (int mt = 0; mt < 2; mt++) {
                int r1 = wr + mt * 16 + lq;
                a[mt][0] = As[r1 * AS_STRIDE + kk + lr];
                a[mt][1] = As[(r1 + 8) * AS_STRIDE + kk + lr];
                a[mt][2] = As[r1 * AS_STRIDE + kk + lr + 4];
                a[mt][3] = As[(r1 + 8) * AS_STRIDE + kk + lr + 4];
            }
            #pragma unroll
            for (int nt = 0; nt < 4; nt++) {
                int c = wc + nt * 8 + lq;
                b[nt][0] = Bs[(kk + lr) * BS_STRIDE + c];
                b[nt][1] = Bs[(kk + lr + 4) * BS_STRIDE + c];
            }
            #pragma unroll
            for (int mt = 0; mt < 2; mt++)
                #pragma unroll
                for (int nt = 0; nt < 4; nt++) {
                    asm volatile(
                        "mma.sync.aligned.m16n8k8.row.col.f32.tf32.tf32.f32 "
                        "{%0,%1,%2,%3}, {%4,%5,%6,%7}, {%8,%9}, {%0,%1,%2,%3};"
                        : "+f"(acc[mt][nt][0]), "+f"(acc[mt][nt][1]),
                          "+f"(acc[mt][nt][2]), "+f"(acc[mt][nt][3])
                        : "r"(a[mt][0]), "r"(a[mt][1]), "r"(a[mt][2]), "r"(a[mt][3]),
                          "r"(b[nt][0]), "r"(b[nt][1]));
                }
        }
        __syncthreads();
    }

    // epilogue: scale by dinv[row], dual store (2 floats per fragment row)
    #pragma unroll
    for (int mt = 0; mt < 2; mt++) {
        int r0 = block_row + wr + mt * 16 + lq;
        int r1 = r0 + 8;
        float d0 = (r0 < M) ? dinv[r0] : 0.0f;
        float d1 = (r1 < M) ? dinv[r1] : 0.0f;
        #pragma unroll
        for (int nt = 0; nt < 4; nt++) {
            int c = block_col + wc + nt * 8 + lr * 2;
            if (r0 < M) {
                float2 v = make_float2(acc[mt][nt][0] * d0, acc[mt][nt][1] * d0);
                *(float2*)&Ht[(size_t)r0 * N + c]  = v;
                *(float2*)&Agg[(size_t)r0 * N + c] = v;
            }
            if (r1 < M) {
                float2 v = make_float2(acc[mt][nt][2] * d1, acc[mt][nt][3] * d1);
                *(float2*)&Ht[(size_t)r1 * N + c]  = v;
                *(float2*)&Agg[(size_t)r1 * N + c] = v;
            }
        }
    }
}

// ---------------- edge scatter: agg[dst] += ht[src] (vector atomics) ----------------
template<int C>
__global__ void scatter_kernel(const float* __restrict__ ht,
                               float* __restrict__ agg) {
    constexpr int CH4 = C / 4;
    int t = blockIdx.x * blockDim.x + threadIdx.x;
    int e = t / CH4;
    int j = t % CH4;
    if (e >= N_EDGES) return;
    int s = g_src[e];
    int d = g_dst[e];
    float4 v = ((const float4*)(ht + (size_t)s * C))[j];
    float4* p = (float4*)(agg + (size_t)d * C) + j;
    asm volatile("red.global.add.v4.f32 [%0], {%1, %2, %3, %4};"
                 :: "l"(p), "f"(v.x), "f"(v.y), "f"(v.z), "f"(v.w)
                 : "memory");
}

// ---------------- epilogue: z = [relu](agg*dinv + b); out = z * sigmoid(z@aw+ab) ----------------
template<int C, bool RELU>
__global__ void gate_kernel(const float* __restrict__ agg,
                            const float* __restrict__ dinv,
                            const float* __restrict__ bias,
                            const float* __restrict__ aw,
                            const float* __restrict__ ab,
                            float* __restrict__ out) {
    int gw   = (blockIdx.x * blockDim.x + threadIdx.x) >> 5;
    int lane = threadIdx.x & 31;
    if (gw >= N_NODES) return;

    float di = dinv[gw];
    float v[C / 32];
    float dot = 0.0f;
    #pragma unroll
    for (int k = 0; k < C / 32; k++) {
        int c = k * 32 + lane;
        float x = agg[(size_t)gw * C + c] * di + bias[c];
        if (RELU) x = fmaxf(x, 0.0f);
        v[k] = x;
        dot += x * aw[c];
    }
    #pragma unroll
    for (int off = 16; off > 0; off >>= 1)
        dot += __shfl_xor_sync(0xffffffffu, dot, off);

    float g = 1.0f / (1.0f + expf(-(dot + ab[0])));
    #pragma unroll
    for (int k = 0; k < C / 32; k++)
        out[(size_t)gw * C + k * 32 + lane] = v[k] * g;
}

// ---------------- launch ----------------
extern "C" void kernel_launch(void* const* d_in, const int* in_sizes, int n_in,
                              void* d_out, int out_size) {
    const float* x    = (const float*)d_in[0];
    const void*  edge = d_in[1];
    const float* W1  = (const float*)d_in[2];
    const float* b1  = (const float*)d_in[3];
    const float* W2  = (const float*)d_in[4];
    const float* b2  = (const float*)d_in[5];
    const float* aw1 = (const float*)d_in[6];
    const float* ab1 = (const float*)d_in[7];
    const float* aw2 = (const float*)d_in[8];
    const float* ab2 = (const float*)d_in[9];
    float* out = (float*)d_out;

    float *dinv, *ht1, *agg1, *ht2, *agg2;
    cudaGetSymbolAddress((void**)&dinv, g_dinv);
    cudaGetSymbolAddress((void**)&ht1,  g_ht1);
    cudaGetSymbolAddress((void**)&agg1, g_agg1);
    cudaGetSymbolAddress((void**)&ht2,  g_ht2);
    cudaGetSymbolAddress((void**)&agg2, g_agg2);

    const int T = 256;

    detect_edge_dtype_kernel<<<1, 32>>>(edge);
    deg_init_kernel<<<(N_NODES + T - 1) / T, T>>>(dinv);
    convert_edges_kernel<<<(2 * N_EDGES + T - 1) / T, T>>>(edge, dinv);
    deg_rsqrt_kernel<<<(N_NODES + T - 1) / T, T>>>(dinv);

    // ---- layer 1: ht1 = agg1 = (x@W1)*dinv ----
    {
        dim3 grid(DIM_HID / BN, (N_NODES + BM - 1) / BM);
        gemm_tf32_kernel<<<grid, 256>>>(x, W1, dinv, ht1, agg1, N_NODES, DIM_IN, DIM_HID);
    }
    scatter_kernel<DIM_HID><<<(N_EDGES * (DIM_HID / 4) + T - 1) / T, T>>>(ht1, agg1);
    gate_kernel<DIM_HID, true><<<(N_NODES * 32 + T - 1) / T, T>>>(agg1, dinv, b1, aw1, ab1, ht1);

    // ---- layer 2: ht2 = agg2 = (y1@W2)*dinv ----
    {
        dim3 grid(DIM_OUT / BN, (N_NODES + BM - 1) / BM);
        gemm_tf32_kernel<<<grid, 256>>>(ht1, W2, dinv, ht2, agg2, N_NODES, DIM_HID, DIM_OUT);
    }
    scatter_kernel<DIM_OUT><<<(N_EDGES * (DIM_OUT / 4) + T - 1) / T, T>>>(ht2, agg2);
    gate_kernel<DIM_OUT, false><<<(N_NODES * 32 + T - 1) / T, T>>>(agg2, dinv, b2, aw2, ab2, out);
}

// round 4
// speedup vs baseline: 1.9733x; 1.0807x over previous
#include <cuda_runtime.h>
#include <math.h>

#define N_NODES 50000
#define N_EDGES 800000
#define DIM_IN  256
#define DIM_HID 128
#define DIM_OUT 64

// ---------------- device scratch (no allocation allowed) ----------------
__device__ float g_dinv[N_NODES];
__device__ float g_ht1[N_NODES * DIM_HID];
__device__ float g_y1 [N_NODES * DIM_HID];
__device__ float g_ht2[N_NODES * DIM_OUT];
__device__ int   g_src[N_EDGES];
__device__ int   g_dst[N_EDGES];
__device__ int   g_cnt[N_NODES];
__device__ int   g_row_ptr[N_NODES + 1];
__device__ int   g_fill[N_NODES];
__device__ int   g_col_idx[N_EDGES];
__device__ int   g_is64;

// ---------------- edge dtype detection ----------------
__global__ void detect_edge_dtype_kernel(const void* edge) {
    if (threadIdx.x == 0 && blockIdx.x == 0) {
        const long long* e64 = (const long long*)edge;
        int ok = 1;
        for (int i = 0; i < 16; i++) {
            long long v = e64[i];
            if (v < 0 || v >= (long long)N_NODES) { ok = 0; break; }
        }
        g_is64 = ok;
    }
}

__global__ void zero_cnt_kernel(int* cnt) {
    int i = blockIdx.x * blockDim.x + threadIdx.x;
    if (i < N_NODES) cnt[i] = 0;
}

// convert edges to int32 AND count in-degree
__global__ void convert_edges_kernel(const void* edge, int* cnt) {
    int i = blockIdx.x * blockDim.x + threadIdx.x;
    if (i >= 2 * N_EDGES) return;
    int v;
    if (g_is64) v = (int)((const long long*)edge)[i];
    else        v = ((const int*)edge)[i];
    if (i < N_EDGES) g_src[i] = v;
    else {
        g_dst[i - N_EDGES] = v;
        atomicAdd(&cnt[v], 1);
    }
}

// single-block exclusive scan over cnt -> row_ptr; also dinv = rsqrt(cnt+1)
__global__ void build_rowptr_kernel(const int* __restrict__ cnt,
                                    int* __restrict__ row_ptr,
                                    float* __restrict__ dinv) {
    __shared__ int warpsum[32];
    const int t = threadIdx.x;            // 1024 threads
    const int lane = t & 31, w = t >> 5;
    const int CHUNK = (N_NODES + 1023) / 1024;   // 49
    int lo = t * CHUNK;
    int hi = lo + CHUNK; if (hi > N_NODES) hi = N_NODES;

    int s = 0;
    for (int i = lo; i < hi; i++) s += cnt[i];

    // inclusive warp scan
    int v = s;
    #pragma unroll
    for (int off = 1; off < 32; off <<= 1) {
        int u = __shfl_up_sync(0xffffffffu, v, off);
        if (lane >= off) v += u;
    }
    if (lane == 31) warpsum[w] = v;
    __syncthreads();
    if (w == 0) {
        int x = warpsum[lane];
        #pragma unroll
        for (int off = 1; off < 32; off <<= 1) {
            int u = __shfl_up_sync(0xffffffffu, x, off);
            if (lane >= off) x += u;
        }
        warpsum[lane] = x;   // inclusive
    }
    __syncthreads();
    int excl = v - s + (w > 0 ? warpsum[w - 1] : 0);

    int run = excl;
    for (int i = lo; i < hi; i++) {
        row_ptr[i] = run;
        int c = cnt[i];
        run += c;
        dinv[i] = rsqrtf((float)c + 1.0f);
    }
    if (t == 1023) row_ptr[N_NODES] = run;
}

__global__ void init_fill_kernel(const int* __restrict__ row_ptr, int* __restrict__ fill) {
    int i = blockIdx.x * blockDim.x + threadIdx.x;
    if (i < N_NODES) fill[i] = row_ptr[i];
}

__global__ void fill_csr_kernel(int* __restrict__ fill, int* __restrict__ col_idx) {
    int e = blockIdx.x * blockDim.x + threadIdx.x;
    if (e >= N_EDGES) return;
    int d = g_dst[e];
    int pos = atomicAdd(&fill[d], 1);
    col_idx[pos] = g_src[e];
}

// ---------------- tf32 helpers ----------------
__device__ __forceinline__ unsigned f2tf32(float f) {
    unsigned u;
    asm("cvt.rna.tf32.f32 %0, %1;" : "=r"(u) : "f"(f));
    return u;
}

// ---------------- tf32 tensor-core GEMM: Ht = (A@B) * dinv[row] ----------------
#define BM 128
#define BN 64
#define BK 32
#define AS_STRIDE 33
#define BS_STRIDE 68

__global__ __launch_bounds__(256)
void gemm_tf32_kernel(const float* __restrict__ A,
                      const float* __restrict__ B,
                      const float* __restrict__ dinv,
                      float* __restrict__ Ht,
                      int M, int K, int N) {
    __shared__ unsigned As[BM * AS_STRIDE];
    __shared__ unsigned Bs[BK * BS_STRIDE];

    const int tid  = threadIdx.x;
    const int warp = tid >> 5;
    const int lane = tid & 31;
    const int wr = (warp & 3) * 32;
    const int wc = (warp >> 2) * 32;
    const int block_row = blockIdx.y * BM;
    const int block_col = blockIdx.x * BN;

    const int lq = lane >> 2;
    const int lr = lane & 3;

    float acc[2][4][4];
    #pragma unroll
    for (int mt = 0; mt < 2; mt++)
        #pragma unroll
        for (int nt = 0; nt < 4; nt++)
            #pragma unroll
            for (int i = 0; i < 4; i++) acc[mt][nt][i] = 0.0f;

    for (int k0 = 0; k0 < K; k0 += BK) {
        #pragma unroll
        for (int l = 0; l < 4; l++) {
            int idx = tid + l * 256;
            int r  = idx >> 3;
            int c4 = idx & 7;
            int gr = block_row + r;
            float4 v = make_float4(0.f, 0.f, 0.f, 0.f);
            if (gr < M)
                v = *(const float4*)&A[(size_t)gr * K + k0 + c4 * 4];
            unsigned* dst = &As[r * AS_STRIDE + c4 * 4];
            dst[0] = f2tf32(v.x); dst[1] = f2tf32(v.y);
            dst[2] = f2tf32(v.z); dst[3] = f2tf32(v.w);
        }
        #pragma unroll
        for (int l = 0; l < 2; l++) {
            int idx = tid + l * 256;
            int r  = idx >> 4;
            int c4 = idx & 15;
            float4 v = *(const float4*)&B[(size_t)(k0 + r) * N + block_col + c4 * 4];
            unsigned* dst = &Bs[r * BS_STRIDE + c4 * 4];
            dst[0] = f2tf32(v.x); dst[1] = f2tf32(v.y);
            dst[2] = f2tf32(v.z); dst[3] = f2tf32(v.w);
        }
        __syncthreads();

        #pragma unroll
        for (int kk = 0; kk < BK; kk += 8) {
            unsigned a[2][4], b[4][2];
            #pragma unroll
            for (int mt = 0; mt < 2; mt++) {
                int r1 = wr + mt * 16 + lq;
                a[mt][0] = As[r1 * AS_STRIDE + kk + lr];
                a[mt][1] = As[(r1 + 8) * AS_STRIDE + kk + lr];
                a[mt][2] = As[r1 * AS_STRIDE + kk + lr + 4];
                a[mt][3] = As[(r1 + 8) * AS_STRIDE + kk + lr + 4];
            }
            #pragma unroll
            for (int nt = 0; nt < 4; nt++) {
                int c = wc + nt * 8 + lq;
                b[nt][0] = Bs[(kk + lr) * BS_STRIDE + c];
                b[nt][1] = Bs[(kk + lr + 4) * BS_STRIDE + c];
            }
            #pragma unroll
            for (int mt = 0; mt < 2; mt++)
                #pragma unroll
                for (int nt = 0; nt < 4; nt++) {
                    asm volatile(
                        "mma.sync.aligned.m16n8k8.row.col.f32.tf32.tf32.f32 "
                        "{%0,%1,%2,%3}, {%4,%5,%6,%7}, {%8,%9}, {%0,%1,%2,%3};"
                        : "+f"(acc[mt][nt][0]), "+f"(acc[mt][nt][1]),
                          "+f"(acc[mt][nt][2]), "+f"(acc[mt][nt][3])
                        : "r"(a[mt][0]), "r"(a[mt][1]), "r"(a[mt][2]), "r"(a[mt][3]),
                          "r"(b[nt][0]), "r"(b[nt][1]));
                }
        }
        __syncthreads();
    }

    #pragma unroll
    for (int mt = 0; mt < 2; mt++) {
        int r0 = block_row + wr + mt * 16 + lq;
        int r1 = r0 + 8;
        float d0 = (r0 < M) ? dinv[r0] : 0.0f;
        float d1 = (r1 < M) ? dinv[r1] : 0.0f;
        #pragma unroll
        for (int nt = 0; nt < 4; nt++) {
            int c = block_col + wc + nt * 8 + lr * 2;
            if (r0 < M)
                *(float2*)&Ht[(size_t)r0 * N + c] =
                    make_float2(acc[mt][nt][0] * d0, acc[mt][nt][1] * d0);
            if (r1 < M)
                *(float2*)&Ht[(size_t)r1 * N + c] =
                    make_float2(acc[mt][nt][2] * d1, acc[mt][nt][3] * d1);
        }
    }
}

// ---------------- fused CSR gather + bias + (relu) + sigmoid gate ----------------
// warp per node: acc = ht[n] + sum_{s in in(n)} ht[s]
//                z = [relu](acc * dinv[n] + b); out = z * sigmoid(z . aw + ab)
template<int C, bool RELU>
__global__ void gather_gate_kernel(const float* __restrict__ ht,
                                   const int* __restrict__ row_ptr,
                                   const int* __restrict__ col_idx,
                                   const float* __restrict__ dinv,
                                   const float* __restrict__ bias,
                                   const float* __restrict__ aw,
                                   const float* __restrict__ ab,
                                   float* __restrict__ out) {
    int gw   = (blockIdx.x * blockDim.x + threadIdx.x) >> 5;
    int lane = threadIdx.x & 31;
    if (gw >= N_NODES) return;

    if constexpr (C == 128) {
        const float4* base = (const float4*)ht;   // 32 float4 per row
        float4 acc = base[(size_t)gw * 32 + lane];  // self loop
        int p = row_ptr[gw], pe = row_ptr[gw + 1];
        for (; p + 4 <= pe; p += 4) {
            int s0 = col_idx[p], s1 = col_idx[p+1], s2 = col_idx[p+2], s3 = col_idx[p+3];
            float4 v0 = base[(size_t)s0 * 32 + lane];
            float4 v1 = base[(size_t)s1 * 32 + lane];
            float4 v2 = base[(size_t)s2 * 32 + lane];
            float4 v3 = base[(size_t)s3 * 32 + lane];
            acc.x += v0.x + v1.x + v2.x + v3.x;
            acc.y += v0.y + v1.y + v2.y + v3.y;
            acc.z += v0.z + v1.z + v2.z + v3.z;
            acc.w += v0.w + v1.w + v2.w + v3.w;
        }
        for (; p < pe; p++) {
            int s = col_idx[p];
            float4 v = base[(size_t)s * 32 + lane];
            acc.x += v.x; acc.y += v.y; acc.z += v.z; acc.w += v.w;
        }
        float di = dinv[gw];
        float4 b = ((const float4*)bias)[lane];
        float4 z;
        z.x = acc.x * di + b.x; z.y = acc.y * di + b.y;
        z.z = acc.z * di + b.z; z.w = acc.w * di + b.w;
        if (RELU) {
            z.x = fmaxf(z.x, 0.f); z.y = fmaxf(z.y, 0.f);
            z.z = fmaxf(z.z, 0.f); z.w = fmaxf(z.w, 0.f);
        }
        float4 a = ((const float4*)aw)[lane];
        float dot = z.x * a.x + z.y * a.y + z.z * a.z + z.w * a.w;
        #pragma unroll
        for (int off = 16; off > 0; off >>= 1)
            dot += __shfl_xor_sync(0xffffffffu, dot, off);
        float g = 1.0f / (1.0f + expf(-(dot + ab[0])));
        z.x *= g; z.y *= g; z.z *= g; z.w *= g;
        ((float4*)out)[(size_t)gw * 32 + lane] = z;
    } else {
        const float2* base = (const float2*)ht;   // 32 float2 per row
        float2 acc = base[(size_t)gw * 32 + lane];
        int p = row_ptr[gw], pe = row_ptr[gw + 1];
        for (; p + 4 <= pe; p += 4) {
            int s0 = col_idx[p], s1 = col_idx[p+1], s2 = col_idx[p+2], s3 = col_idx[p+3];
            float2 v0 = base[(size_t)s0 * 32 + lane];
            float2 v1 = base[(size_t)s1 * 32 + lane];
            float2 v2 = base[(size_t)s2 * 32 + lane];
            float2 v3 = base[(size_t)s3 * 32 + lane];
            acc.x += v0.x + v1.x + v2.x + v3.x;
            acc.y += v0.y + v1.y + v2.y + v3.y;
        }
        for (; p < pe; p++) {
            int s = col_idx[p];
            float2 v = base[(size_t)s * 32 + lane];
            acc.x += v.x; acc.y += v.y;
        }
        float di = dinv[gw];
        float2 b = ((const float2*)bias)[lane];
        float2 z;
        z.x = acc.x * di + b.x; z.y = acc.y * di + b.y;
        if (RELU) { z.x = fmaxf(z.x, 0.f); z.y = fmaxf(z.y, 0.f); }
        float2 a = ((const float2*)aw)[lane];
        float dot = z.x * a.x + z.y * a.y;
        #pragma unroll
        for (int off = 16; off > 0; off >>= 1)
            dot += __shfl_xor_sync(0xffffffffu, dot, off);
        float g = 1.0f / (1.0f + expf(-(dot + ab[0])));
        z.x *= g; z.y *= g;
        ((float2*)out)[(size_t)gw * 32 + lane] = z;
    }
}

// ---------------- launch ----------------
extern "C" void kernel_launch(void* const* d_in, const int* in_sizes, int n_in,
                              void* d_out, int out_size) {
    const float* x    = (const float*)d_in[0];
    const void*  edge = d_in[1];
    const float* W1  = (const float*)d_in[2];
    const float* b1  = (const float*)d_in[3];
    const float* W2  = (const float*)d_in[4];
    const float* b2  = (const float*)d_in[5];
    const float* aw1 = (const float*)d_in[6];
    const float* ab1 = (const float*)d_in[7];
    const float* aw2 = (const float*)d_in[8];
    const float* ab2 = (const float*)d_in[9];
    float* out = (float*)d_out;

    float *dinv, *ht1, *y1, *ht2;
    int *cnt, *row_ptr, *fill, *col_idx;
    cudaGetSymbolAddress((void**)&dinv,    g_dinv);
    cudaGetSymbolAddress((void**)&ht1,     g_ht1);
    cudaGetSymbolAddress((void**)&y1,      g_y1);
    cudaGetSymbolAddress((void**)&ht2,     g_ht2);
    cudaGetSymbolAddress((void**)&cnt,     g_cnt);
    cudaGetSymbolAddress((void**)&row_ptr, g_row_ptr);
    cudaGetSymbolAddress((void**)&fill,    g_fill);
    cudaGetSymbolAddress((void**)&col_idx, g_col_idx);

    const int T = 256;

    // ---- CSR build ----
    detect_edge_dtype_kernel<<<1, 32>>>(edge);
    zero_cnt_kernel<<<(N_NODES + T - 1) / T, T>>>(cnt);
    convert_edges_kernel<<<(2 * N_EDGES + T - 1) / T, T>>>(edge, cnt);
    build_rowptr_kernel<<<1, 1024>>>(cnt, row_ptr, dinv);
    init_fill_kernel<<<(N_NODES + T - 1) / T, T>>>(row_ptr, fill);
    fill_csr_kernel<<<(N_EDGES + T - 1) / T, T>>>(fill, col_idx);

    // ---- layer 1 ----
    {
        dim3 grid(DIM_HID / BN, (N_NODES + BM - 1) / BM);
        gemm_tf32_kernel<<<grid, 256>>>(x, W1, dinv, ht1, N_NODES, DIM_IN, DIM_HID);
    }
    gather_gate_kernel<DIM_HID, true><<<(N_NODES * 32 + T - 1) / T, T>>>(
        ht1, row_ptr, col_idx, dinv, b1, aw1, ab1, y1);

    // ---- layer 2 ----
    {
        dim3 grid(DIM_OUT / BN, (N_NODES + BM - 1) / BM);
        gemm_tf32_kernel<<<grid, 256>>>(y1, W2, dinv, ht2, N_NODES, DIM_HID, DIM_OUT);
    }
    gather_gate_kernel<DIM_OUT, false><<<(N_NODES * 32 + T - 1) / T, T>>>(
        ht2, row_ptr, col_idx, dinv, b2, aw2, ab2, out);
}

// round 5
// speedup vs baseline: 3.0515x; 1.5464x over previous
#include <cuda_runtime.h>
#include <math.h>

#define N_NODES 50000
#define N_EDGES 800000
#define DIM_IN  256
#define DIM_HID 128
#define DIM_OUT 64
#define SCAN_BLOCKS ((N_NODES + 1023) / 1024)   // 49

// ---------------- device scratch (no allocation allowed) ----------------
__device__ float g_dinv[N_NODES];
__device__ float g_h1[N_NODES * DIM_HID];
__device__ float g_y1[N_NODES * DIM_HID];
__device__ float g_h2[N_NODES * DIM_OUT];
__device__ int   g_src[N_EDGES];
__device__ int   g_dst[N_EDGES];
__device__ int   g_cnt[N_NODES];
__device__ int   g_row_ptr[N_NODES + 1];
__device__ int   g_fill[N_NODES];
__device__ int   g_col_idx[N_EDGES];
__device__ int   g_blocksum[64];
__device__ int   g_is64;

// ---------------- edge dtype detection ----------------
__global__ void detect_edge_dtype_kernel(const void* edge) {
    if (threadIdx.x == 0 && blockIdx.x == 0) {
        const long long* e64 = (const long long*)edge;
        int ok = 1;
        for (int i = 0; i < 16; i++) {
            long long v = e64[i];
            if (v < 0 || v >= (long long)N_NODES) { ok = 0; break; }
        }
        g_is64 = ok;
    }
}

__global__ void zero_cnt_kernel(int* cnt) {
    int i = blockIdx.x * blockDim.x + threadIdx.x;
    if (i < N_NODES) cnt[i] = 0;
}

// convert edges to int32 AND count in-degree
__global__ void convert_edges_kernel(const void* edge, int* cnt) {
    int i = blockIdx.x * blockDim.x + threadIdx.x;
    if (i >= 2 * N_EDGES) return;
    int v;
    if (g_is64) v = (int)((const long long*)edge)[i];
    else        v = ((const int*)edge)[i];
    if (i < N_EDGES) g_src[i] = v;
    else {
        g_dst[i - N_EDGES] = v;
        atomicAdd(&cnt[v], 1);
    }
}

// ---------------- parallel 3-phase scan ----------------
// phase 1: per-block scan of cnt -> local exclusive into row_ptr; blocksum; dinv
__global__ __launch_bounds__(1024)
void scan_block_kernel(const int* __restrict__ cnt,
                       int* __restrict__ row_ptr,
                       float* __restrict__ dinv,
                       int* __restrict__ blocksum) {
    __shared__ int ws[32];
    const int t = threadIdx.x;
    const int lane = t & 31, w = t >> 5;
    const int i = blockIdx.x * 1024 + t;

    int val = (i < N_NODES) ? cnt[i] : 0;
    int v = val;
    #pragma unroll
    for (int off = 1; off < 32; off <<= 1) {
        int u = __shfl_up_sync(0xffffffffu, v, off);
        if (lane >= off) v += u;
    }
    if (lane == 31) ws[w] = v;
    __syncthreads();
    if (w == 0) {
        int x = ws[lane];
        #pragma unroll
        for (int off = 1; off < 32; off <<= 1) {
            int u = __shfl_up_sync(0xffffffffu, x, off);
            if (lane >= off) x += u;
        }
        ws[lane] = x;
    }
    __syncthreads();
    int incl = v + (w > 0 ? ws[w - 1] : 0);
    if (i < N_NODES) {
        row_ptr[i] = incl - val;                 // local exclusive
        dinv[i] = rsqrtf((float)val + 1.0f);
    }
    if (t == 1023) blocksum[blockIdx.x] = incl;
}

// phase 2: exclusive scan of blocksums (49 values), in place; sets row_ptr[N]
__global__ void scan_tops_kernel(int* __restrict__ blocksum, int* __restrict__ row_ptr) {
    __shared__ int wtot;
    const int t = threadIdx.x;   // 64 threads
    const int lane = t & 31, w = t >> 5;
    int val = (t < SCAN_BLOCKS) ? blocksum[t] : 0;
    int v = val;
    #pragma unroll
    for (int off = 1; off < 32; off <<= 1) {
        int u = __shfl_up_sync(0xffffffffu, v, off);
        if (lane >= off) v += u;
    }
    if (w == 0 && lane == 31) wtot = v;
    __syncthreads();
    if (w == 1) v += wtot;
    __syncthreads();
    if (t < SCAN_BLOCKS) blocksum[t] = v - val;   // exclusive
    if (t == SCAN_BLOCKS - 1) row_ptr[N_NODES] = v;  // grand total
}

// phase 3: add block offsets; also init fill
__global__ __launch_bounds__(1024)
void scan_add_kernel(int* __restrict__ row_ptr,
                     const int* __restrict__ blocksum,
                     int* __restrict__ fill) {
    const int i = blockIdx.x * 1024 + threadIdx.x;
    if (i < N_NODES) {
        int r = row_ptr[i] + blocksum[blockIdx.x];
        row_ptr[i] = r;
        fill[i] = r;
    }
}

__global__ void fill_csr_kernel(int* __restrict__ fill, int* __restrict__ col_idx) {
    int e = blockIdx.x * blockDim.x + threadIdx.x;
    if (e >= N_EDGES) return;
    int d = g_dst[e];
    int pos = atomicAdd(&fill[d], 1);
    col_idx[pos] = g_src[e];
}

// ---------------- tf32 helpers ----------------
__device__ __forceinline__ unsigned f2tf32(float f) {
    unsigned u;
    asm("cvt.rna.tf32.f32 %0, %1;" : "=r"(u) : "f"(f));
    return u;
}

// ---------------- tf32 tensor-core GEMM: H = A@B (no scaling) ----------------
#define BM 128
#define BN 64
#define BK 32
#define AS_STRIDE 33
#define BS_STRIDE 68

__global__ __launch_bounds__(256)
void gemm_tf32_kernel(const float* __restrict__ A,
                      const float* __restrict__ B,
                      float* __restrict__ H,
                      int M, int K, int N) {
    __shared__ unsigned As[BM * AS_STRIDE];
    __shared__ unsigned Bs[BK * BS_STRIDE];

    const int tid  = threadIdx.x;
    const int warp = tid >> 5;
    const int lane = tid & 31;
    const int wr = (warp & 3) * 32;
    const int wc = (warp >> 2) * 32;
    const int block_row = blockIdx.y * BM;
    const int block_col = blockIdx.x * BN;

    const int lq = lane >> 2;
    const int lr = lane & 3;

    float acc[2][4][4];
    #pragma unroll
    for (int mt = 0; mt < 2; mt++)
        #pragma unroll
        for (int nt = 0; nt < 4; nt++)
            #pragma unroll
            for (int i = 0; i < 4; i++) acc[mt][nt][i] = 0.0f;

    for (int k0 = 0; k0 < K; k0 += BK) {
        #pragma unroll
        for (int l = 0; l < 4; l++) {
            int idx = tid + l * 256;
            int r  = idx >> 3;
            int c4 = idx & 7;
            int gr = block_row + r;
            float4 v = make_float4(0.f, 0.f, 0.f, 0.f);
            if (gr < M)
                v = *(const float4*)&A[(size_t)gr * K + k0 + c4 * 4];
            unsigned* dst = &As[r * AS_STRIDE + c4 * 4];
            dst[0] = f2tf32(v.x); dst[1] = f2tf32(v.y);
            dst[2] = f2tf32(v.z); dst[3] = f2tf32(v.w);
        }
        #pragma unroll
        for (int l = 0; l < 2; l++) {
            int idx = tid + l * 256;
            int r  = idx >> 4;
            int c4 = idx & 15;
            float4 v = *(const float4*)&B[(size_t)(k0 + r) * N + block_col + c4 * 4];
            unsigned* dst = &Bs[r * BS_STRIDE + c4 * 4];
            dst[0] = f2tf32(v.x); dst[1] = f2tf32(v.y);
            dst[2] = f2tf32(v.z); dst[3] = f2tf32(v.w);
        }
        __syncthreads();

        #pragma unroll
        for (int kk = 0; kk < BK; kk += 8) {
            unsigned a[2][4], b[4][2];
            #pragma unroll
            for (int mt = 0; mt < 2; mt++) {
                int r1 = wr + mt * 16 + lq;
                a[mt][0] = As[r1 * AS_STRIDE + kk + lr];
                a[mt][1] = As[(r1 + 8) * AS_STRIDE + kk + lr];
                a[mt][2] = As[r1 * AS_STRIDE + kk + lr + 4];
                a[mt][3] = As[(r1 + 8) * AS_STRIDE + kk + lr + 4];
            }
            #pragma unroll
            for (int nt = 0; nt < 4; nt++) {
                int c = wc + nt * 8 + lq;
                b[nt][0] = Bs[(kk + lr) * BS_STRIDE + c];
                b[nt][1] = Bs[(kk + lr + 4) * BS_STRIDE + c];
            }
            #pragma unroll
            for (int mt = 0; mt < 2; mt++)
                #pragma unroll
                for (int nt = 0; nt < 4; nt++) {
                    asm volatile(
                        "mma.sync.aligned.m16n8k8.row.col.f32.tf32.tf32.f32 "
                        "{%0,%1,%2,%3}, {%4,%5,%6,%7}, {%8,%9}, {%0,%1,%2,%3};"
                        : "+f"(acc[mt][nt][0]), "+f"(acc[mt][nt][1]),
                          "+f"(acc[mt][nt][2]), "+f"(acc[mt][nt][3])
                        : "r"(a[mt][0]), "r"(a[mt][1]), "r"(a[mt][2]), "r"(a[mt][3]),
                          "r"(b[nt][0]), "r"(b[nt][1]));
                }
        }
        __syncthreads();
    }

    #pragma unroll
    for (int mt = 0; mt < 2; mt++) {
        int r0 = block_row + wr + mt * 16 + lq;
        int r1 = r0 + 8;
        #pragma unroll
        for (int nt = 0; nt < 4; nt++) {
            int c = block_col + wc + nt * 8 + lr * 2;
            if (r0 < M)
                *(float2*)&H[(size_t)r0 * N + c] = make_float2(acc[mt][nt][0], acc[mt][nt][1]);
            if (r1 < M)
                *(float2*)&H[(size_t)r1 * N + c] = make_float2(acc[mt][nt][2], acc[mt][nt][3]);
        }
    }
}

// ---------------- fused CSR gather (per-src dinv) + bias + (relu) + gate ----------------
// acc = dinv[n]*h[n] + sum_s dinv[s]*h[s];  z = [relu](acc*dinv[n] + b);
// out = z * sigmoid(z . aw + ab)
template<int C, bool RELU>
__global__ void gather_gate_kernel(const float* __restrict__ h,
                                   const int* __restrict__ row_ptr,
                                   const int* __restrict__ col_idx,
                                   const float* __restrict__ dinv,
                                   const float* __restrict__ bias,
                                   const float* __restrict__ aw,
                                   const float* __restrict__ ab,
                                   float* __restrict__ out) {
    int gw   = (blockIdx.x * blockDim.x + threadIdx.x) >> 5;
    int lane = threadIdx.x & 31;
    if (gw >= N_NODES) return;

    float di = dinv[gw];

    if constexpr (C == 128) {
        const float4* base = (const float4*)h;
        float4 acc = base[(size_t)gw * 32 + lane];
        acc.x *= di; acc.y *= di; acc.z *= di; acc.w *= di;   // self loop
        int p = row_ptr[gw], pe = row_ptr[gw + 1];
        for (; p + 4 <= pe; p += 4) {
            int s0 = col_idx[p], s1 = col_idx[p+1], s2 = col_idx[p+2], s3 = col_idx[p+3];
            float w0 = dinv[s0], w1 = dinv[s1], w2 = dinv[s2], w3 = dinv[s3];
            float4 v0 = base[(size_t)s0 * 32 + lane];
            float4 v1 = base[(size_t)s1 * 32 + lane];
            float4 v2 = base[(size_t)s2 * 32 + lane];
            float4 v3 = base[(size_t)s3 * 32 + lane];
            acc.x += v0.x*w0 + v1.x*w1 + v2.x*w2 + v3.x*w3;
            acc.y += v0.y*w0 + v1.y*w1 + v2.y*w2 + v3.y*w3;
            acc.z += v0.z*w0 + v1.z*w1 + v2.z*w2 + v3.z*w3;
            acc.w += v0.w*w0 + v1.w*w1 + v2.w*w2 + v3.w*w3;
        }
        for (; p < pe; p++) {
            int s = col_idx[p];
            float w = dinv[s];
            float4 v = base[(size_t)s * 32 + lane];
            acc.x += v.x*w; acc.y += v.y*w; acc.z += v.z*w; acc.w += v.w*w;
        }
        float4 b = ((const float4*)bias)[lane];
        float4 z;
        z.x = acc.x * di + b.x; z.y = acc.y * di + b.y;
        z.z = acc.z * di + b.z; z.w = acc.w * di + b.w;
        if (RELU) {
            z.x = fmaxf(z.x, 0.f); z.y = fmaxf(z.y, 0.f);
            z.z = fmaxf(z.z, 0.f); z.w = fmaxf(z.w, 0.f);
        }
        float4 a = ((const float4*)aw)[lane];
        float dot = z.x * a.x + z.y * a.y + z.z * a.z + z.w * a.w;
        #pragma unroll
        for (int off = 16; off > 0; off >>= 1)
            dot += __shfl_xor_sync(0xffffffffu, dot, off);
        float g = 1.0f / (1.0f + expf(-(dot + ab[0])));
        z.x *= g; z.y *= g; z.z *= g; z.w *= g;
        ((float4*)out)[(size_t)gw * 32 + lane] = z;
    } else {
        const float2* base = (const float2*)h;
        float2 acc = base[(size_t)gw * 32 + lane];
        acc.x *= di; acc.y *= di;
        int p = row_ptr[gw], pe = row_ptr[gw + 1];
        for (; p + 4 <= pe; p += 4) {
            int s0 = col_idx[p], s1 = col_idx[p+1], s2 = col_idx[p+2], s3 = col_idx[p+3];
            float w0 = dinv[s0], w1 = dinv[s1], w2 = dinv[s2], w3 = dinv[s3];
            float2 v0 = base[(size_t)s0 * 32 + lane];
            float2 v1 = base[(size_t)s1 * 32 + lane];
            float2 v2 = base[(size_t)s2 * 32 + lane];
            float2 v3 = base[(size_t)s3 * 32 + lane];
            acc.x += v0.x*w0 + v1.x*w1 + v2.x*w2 + v3.x*w3;
            acc.y += v0.y*w0 + v1.y*w1 + v2.y*w2 + v3.y*w3;
        }
        for (; p < pe; p++) {
            int s = col_idx[p];
            float w = dinv[s];
            float2 v = base[(size_t)s * 32 + lane];
            acc.x += v.x*w; acc.y += v.y*w;
        }
        float2 b = ((const float2*)bias)[lane];
        float2 z;
        z.x = acc.x * di + b.x; z.y = acc.y * di + b.y;
        if (RELU) { z.x = fmaxf(z.x, 0.f); z.y = fmaxf(z.y, 0.f); }
        float2 a = ((const float2*)aw)[lane];
        float dot = z.x * a.x + z.y * a.y;
        #pragma unroll
        for (int off = 16; off > 0; off >>= 1)
            dot += __shfl_xor_sync(0xffffffffu, dot, off);
        float g = 1.0f / (1.0f + expf(-(dot + ab[0])));
        z.x *= g; z.y *= g;
        ((float2*)out)[(size_t)gw * 32 + lane] = z;
    }
}

// ---------------- launch ----------------
extern "C" void kernel_launch(void* const* d_in, const int* in_sizes, int n_in,
                              void* d_out, int out_size) {
    const float* x    = (const float*)d_in[0];
    const void*  edge = d_in[1];
    const float* W1  = (const float*)d_in[2];
    const float* b1  = (const float*)d_in[3];
    const float* W2  = (const float*)d_in[4];
    const float* b2  = (const float*)d_in[5];
    const float* aw1 = (const float*)d_in[6];
    const float* ab1 = (const float*)d_in[7];
    const float* aw2 = (const float*)d_in[8];
    const float* ab2 = (const float*)d_in[9];
    float* out = (float*)d_out;

    float *dinv, *h1, *y1, *h2;
    int *cnt, *row_ptr, *fill, *col_idx, *blocksum;
    cudaGetSymbolAddress((void**)&dinv,     g_dinv);
    cudaGetSymbolAddress((void**)&h1,       g_h1);
    cudaGetSymbolAddress((void**)&y1,       g_y1);
    cudaGetSymbolAddress((void**)&h2,       g_h2);
    cudaGetSymbolAddress((void**)&cnt,      g_cnt);
    cudaGetSymbolAddress((void**)&row_ptr,  g_row_ptr);
    cudaGetSymbolAddress((void**)&fill,     g_fill);
    cudaGetSymbolAddress((void**)&col_idx,  g_col_idx);
    cudaGetSymbolAddress((void**)&blocksum, g_blocksum);

    // side stream + events, created once on the (uncaptured) correctness call
    static cudaStream_t s1 = nullptr;
    static cudaEvent_t evA = nullptr, evB = nullptr;
    if (s1 == nullptr) {
        cudaStreamCreateWithFlags(&s1, cudaStreamNonBlocking);
        cudaEventCreateWithFlags(&evA, cudaEventDisableTiming);
        cudaEventCreateWithFlags(&evB, cudaEventDisableTiming);
    }

    const int T = 256;

    // fork: CSR build chain on s1, GEMM1 on main stream
    detect_edge_dtype_kernel<<<1, 32>>>(edge);
    cudaEventRecord(evA, 0);
    cudaStreamWaitEvent(s1, evA, 0);

    zero_cnt_kernel<<<(N_NODES + T - 1) / T, T, 0, s1>>>(cnt);
    convert_edges_kernel<<<(2 * N_EDGES + T - 1) / T, T, 0, s1>>>(edge, cnt);
    scan_block_kernel<<<SCAN_BLOCKS, 1024, 0, s1>>>(cnt, row_ptr, dinv, blocksum);
    scan_tops_kernel<<<1, 64, 0, s1>>>(blocksum, row_ptr);
    scan_add_kernel<<<SCAN_BLOCKS, 1024, 0, s1>>>(row_ptr, blocksum, fill);
    fill_csr_kernel<<<(N_EDGES + T - 1) / T, T, 0, s1>>>(fill, col_idx);
    cudaEventRecord(evB, s1);

    // GEMM1 (independent of edges now)
    {
        dim3 grid(DIM_HID / BN, (N_NODES + BM - 1) / BM);
        gemm_tf32_kernel<<<grid, 256>>>(x, W1, h1, N_NODES, DIM_IN, DIM_HID);
    }

    // join
    cudaStreamWaitEvent(0, evB, 0);

    gather_gate_kernel<DIM_HID, true><<<(N_NODES * 32 + T - 1) / T, T>>>(
        h1, row_ptr, col_idx, dinv, b1, aw1, ab1, y1);

    {
        dim3 grid(DIM_OUT / BN, (N_NODES + BM - 1) / BM);
        gemm_tf32_kernel<<<grid, 256>>>(y1, W2, h2, N_NODES, DIM_HID, DIM_OUT);
    }
    gather_gate_kernel<DIM_OUT, false><<<(N_NODES * 32 + T - 1) / T, T>>>(
        h2, row_ptr, col_idx, dinv, b2, aw2, ab2, out);
}

// round 7
// speedup vs baseline: 3.0798x; 1.0093x over previous
#include <cuda_runtime.h>
#include <cuda_fp16.h>
#include <math.h>

#define N_NODES 50000
#define N_EDGES 800000
#define DIM_IN  256
#define DIM_HID 128
#define DIM_OUT 64
#define SCAN_BLOCKS ((N_NODES + 1023) / 1024)   // 49

// ---------------- device scratch (no allocation allowed) ----------------
__device__ float g_dinv[N_NODES];
__device__ __half g_h1[N_NODES * DIM_HID];   // GEMM1 out (fp16)
__device__ float  g_y1[N_NODES * DIM_HID];   // gather1 out (fp32, GEMM2 in)
__device__ __half g_h2[N_NODES * DIM_OUT];   // GEMM2 out (fp16)
__device__ int   g_src[N_EDGES];
__device__ int   g_dst[N_EDGES];
__device__ int   g_cnt[N_NODES];
__device__ int   g_row_ptr[N_NODES + 1];
__device__ int   g_fill[N_NODES];
__device__ int   g_col_idx[N_EDGES];
__device__ int   g_blocksum[64];
__device__ int   g_is64;

// ---------------- edge dtype detection ----------------
__global__ void detect_edge_dtype_kernel(const void* edge) {
    if (threadIdx.x == 0 && blockIdx.x == 0) {
        const long long* e64 = (const long long*)edge;
        int ok = 1;
        for (int i = 0; i < 16; i++) {
            long long v = e64[i];
            if (v < 0 || v >= (long long)N_NODES) { ok = 0; break; }
        }
        g_is64 = ok;
    }
}

__global__ void zero_cnt_kernel(int* cnt) {
    int i = blockIdx.x * blockDim.x + threadIdx.x;
    if (i < N_NODES) cnt[i] = 0;
}

// convert edges to int32 AND count in-degree
__global__ void convert_edges_kernel(const void* edge, int* cnt) {
    int i = blockIdx.x * blockDim.x + threadIdx.x;
    if (i >= 2 * N_EDGES) return;
    int v;
    if (g_is64) v = (int)((const long long*)edge)[i];
    else        v = ((const int*)edge)[i];
    if (i < N_EDGES) g_src[i] = v;
    else {
        g_dst[i - N_EDGES] = v;
        atomicAdd(&cnt[v], 1);
    }
}

// ---------------- parallel 3-phase scan ----------------
__global__ __launch_bounds__(1024)
void scan_block_kernel(const int* __restrict__ cnt,
                       int* __restrict__ row_ptr,
                       float* __restrict__ dinv,
                       int* __restrict__ blocksum) {
    __shared__ int ws[32];
    const int t = threadIdx.x;
    const int lane = t & 31, w = t >> 5;
    const int i = blockIdx.x * 1024 + t;

    int val = (i < N_NODES) ? cnt[i] : 0;
    int v = val;
    #pragma unroll
    for (int off = 1; off < 32; off <<= 1) {
        int u = __shfl_up_sync(0xffffffffu, v, off);
        if (lane >= off) v += u;
    }
    if (lane == 31) ws[w] = v;
    __syncthreads();
    if (w == 0) {
        int x = ws[lane];
        #pragma unroll
        for (int off = 1; off < 32; off <<= 1) {
            int u = __shfl_up_sync(0xffffffffu, x, off);
            if (lane >= off) x += u;
        }
        ws[lane] = x;
    }
    __syncthreads();
    int incl = v + (w > 0 ? ws[w - 1] : 0);
    if (i < N_NODES) {
        row_ptr[i] = incl - val;
        dinv[i] = rsqrtf((float)val + 1.0f);
    }
    if (t == 1023) blocksum[blockIdx.x] = incl;
}

__global__ void scan_tops_kernel(int* __restrict__ blocksum, int* __restrict__ row_ptr) {
    __shared__ int wtot;
    const int t = threadIdx.x;   // 64 threads
    const int lane = t & 31, w = t >> 5;
    int val = (t < SCAN_BLOCKS) ? blocksum[t] : 0;
    int v = val;
    #pragma unroll
    for (int off = 1; off < 32; off <<= 1) {
        int u = __shfl_up_sync(0xffffffffu, v, off);
        if (lane >= off) v += u;
    }
    if (w == 0 && lane == 31) wtot = v;
    __syncthreads();
    if (w == 1) v += wtot;
    __syncthreads();
    if (t < SCAN_BLOCKS) blocksum[t] = v - val;
    if (t == SCAN_BLOCKS - 1) row_ptr[N_NODES] = v;
}

__global__ __launch_bounds__(1024)
void scan_add_kernel(int* __restrict__ row_ptr,
                     const int* __restrict__ blocksum,
                     int* __restrict__ fill) {
    const int i = blockIdx.x * 1024 + threadIdx.x;
    if (i < N_NODES) {
        int r = row_ptr[i] + blocksum[blockIdx.x];
        row_ptr[i] = r;
        fill[i] = r;
    }
}

__global__ void fill_csr_kernel(int* __restrict__ fill, int* __restrict__ col_idx) {
    int e = blockIdx.x * blockDim.x + threadIdx.x;
    if (e >= N_EDGES) return;
    int d = g_dst[e];
    int pos = atomicAdd(&fill[d], 1);
    col_idx[pos] = g_src[e];
}

// ---------------- tf32 helpers ----------------
__device__ __forceinline__ unsigned f2tf32(float f) {
    unsigned u;
    asm("cvt.rna.tf32.f32 %0, %1;" : "=r"(u) : "f"(f));
    return u;
}

// ---------------- tf32 tensor-core GEMM: H(fp16) = A@B ----------------
#define BM 128
#define BN 64
#define BK 32
#define AS_STRIDE 33
#define BS_STRIDE 68

__global__ __launch_bounds__(256)
void gemm_tf32_kernel(const float* __restrict__ A,
                      const float* __restrict__ B,
                      __half* __restrict__ H,
                      int M, int K, int N) {
    __shared__ unsigned As[BM * AS_STRIDE];
    __shared__ unsigned Bs[BK * BS_STRIDE];

    const int tid  = threadIdx.x;
    const int warp = tid >> 5;
    const int lane = tid & 31;
    const int wr = (warp & 3) * 32;
    const int wc = (warp >> 2) * 32;
    const int block_row = blockIdx.y * BM;
    const int block_col = blockIdx.x * BN;

    const int lq = lane >> 2;
    const int lr = lane & 3;

    float acc[2][4][4];
    #pragma unroll
    for (int mt = 0; mt < 2; mt++)
        #pragma unroll
        for (int nt = 0; nt < 4; nt++)
            #pragma unroll
            for (int i = 0; i < 4; i++) acc[mt][nt][i] = 0.0f;

    for (int k0 = 0; k0 < K; k0 += BK) {
        #pragma unroll
        for (int l = 0; l < 4; l++) {
            int idx = tid + l * 256;
            int r  = idx >> 3;
            int c4 = idx & 7;
            int gr = block_row + r;
            float4 v = make_float4(0.f, 0.f, 0.f, 0.f);
            if (gr < M)
                v = *(const float4*)&A[(size_t)gr * K + k0 + c4 * 4];
            unsigned* dst = &As[r * AS_STRIDE + c4 * 4];
            dst[0] = f2tf32(v.x); dst[1] = f2tf32(v.y);
            dst[2] = f2tf32(v.z); dst[3] = f2tf32(v.w);
        }
        #pragma unroll
        for (int l = 0; l < 2; l++) {
            int idx = tid + l * 256;
            int r  = idx >> 4;
            int c4 = idx & 15;
            float4 v = *(const float4*)&B[(size_t)(k0 + r) * N + block_col + c4 * 4];
            unsigned* dst = &Bs[r * BS_STRIDE + c4 * 4];
            dst[0] = f2tf32(v.x); dst[1] = f2tf32(v.y);
            dst[2] = f2tf32(v.z); dst[3] = f2tf32(v.w);
        }
        __syncthreads();

        #pragma unroll
        for (int kk = 0; kk < BK; kk += 8) {
            unsigned a[2][4], b[4][2];
            #pragma unroll
            for (int mt = 0; mt < 2; mt++) {
                int r1 = wr + mt * 16 + lq;
                a[mt][0] = As[r1 * AS_STRIDE + kk + lr];
                a[mt][1] = As[(r1 + 8) * AS_STRIDE + kk + lr];
                a[mt][2] = As[r1 * AS_STRIDE + kk + lr + 4];
                a[mt][3] = As[(r1 + 8) * AS_STRIDE + kk + lr + 4];
            }
            #pragma unroll
            for (int nt = 0; nt < 4; nt++) {
                int c = wc + nt * 8 + lq;
                b[nt][0] = Bs[(kk + lr) * BS_STRIDE + c];
                b[nt][1] = Bs[(kk + lr + 4) * BS_STRIDE + c];
            }
            #pragma unroll
            for (int mt = 0; mt < 2; mt++)
                #pragma unroll
                for (int nt = 0; nt < 4; nt++) {
                    asm volatile(
                        "mma.sync.aligned.m16n8k8.row.col.f32.tf32.tf32.f32 "
                        "{%0,%1,%2,%3}, {%4,%5,%6,%7}, {%8,%9}, {%0,%1,%2,%3};"
                        : "+f"(acc[mt][nt][0]), "+f"(acc[mt][nt][1]),
                          "+f"(acc[mt][nt][2]), "+f"(acc[mt][nt][3])
                        : "r"(a[mt][0]), "r"(a[mt][1]), "r"(a[mt][2]), "r"(a[mt][3]),
                          "r"(b[nt][0]), "r"(b[nt][1]));
                }
        }
        __syncthreads();
    }

    // epilogue: pack pairs to half2 and store
    #pragma unroll
    for (int mt = 0; mt < 2; mt++) {
        int r0 = block_row + wr + mt * 16 + lq;
        int r1 = r0 + 8;
        #pragma unroll
        for (int nt = 0; nt < 4; nt++) {
            int c = block_col + wc + nt * 8 + lr * 2;
            if (r0 < M) {
                __half2 v = __floats2half2_rn(acc[mt][nt][0], acc[mt][nt][1]);
                *(__half2*)&H[(size_t)r0 * N + c] = v;
            }
            if (r1 < M) {
                __half2 v = __floats2half2_rn(acc[mt][nt][2], acc[mt][nt][3]);
                *(__half2*)&H[(size_t)r1 * N + c] = v;
            }
        }
    }
}

// ---------------- fused CSR gather (fp16 in, fp32 out) + bias + (relu) + gate ----------------
// acc = dinv[n]*h[n] + sum_s dinv[s]*h[s];  z = [relu](acc*dinv[n] + b);
// out = z * sigmoid(z . aw + ab)
template<int C, bool RELU>
__global__ void gather_gate_kernel(const __half* __restrict__ h,
                                   const int* __restrict__ row_ptr,
                                   const int* __restrict__ col_idx,
                                   const float* __restrict__ dinv,
                                   const float* __restrict__ bias,
                                   const float* __restrict__ aw,
                                   const float* __restrict__ ab,
                                   float* __restrict__ out) {
    int gw   = (blockIdx.x * blockDim.x + threadIdx.x) >> 5;
    int lane = threadIdx.x & 31;
    if (gw >= N_NODES) return;

    float di = dinv[gw];

    if constexpr (C == 128) {
        // lane handles 4 channels (uint2 = 2x half2, 8B load)
        const uint2* base = (const uint2*)h;   // 32 uint2 per row
        uint2 u = base[(size_t)gw * 32 + lane];
        float2 p0 = __half22float2(*(__half2*)&u.x);
        float2 p1 = __half22float2(*(__half2*)&u.y);
        float4 acc = make_float4(p0.x * di, p0.y * di, p1.x * di, p1.y * di);

        int p = row_ptr[gw], pe = row_ptr[gw + 1];
        for (; p + 4 <= pe; p += 4) {
            int s0 = col_idx[p], s1 = col_idx[p+1], s2 = col_idx[p+2], s3 = col_idx[p+3];
            float w0 = dinv[s0], w1 = dinv[s1], w2 = dinv[s2], w3 = dinv[s3];
            uint2 u0 = base[(size_t)s0 * 32 + lane];
            uint2 u1 = base[(size_t)s1 * 32 + lane];
            uint2 u2 = base[(size_t)s2 * 32 + lane];
            uint2 u3 = base[(size_t)s3 * 32 + lane];
            float2 a0 = __half22float2(*(__half2*)&u0.x);
            float2 b0 = __half22float2(*(__half2*)&u0.y);
            float2 a1 = __half22float2(*(__half2*)&u1.x);
            float2 b1 = __half22float2(*(__half2*)&u1.y);
            float2 a2 = __half22float2(*(__half2*)&u2.x);
            float2 b2 = __half22float2(*(__half2*)&u2.y);
            float2 a3 = __half22float2(*(__half2*)&u3.x);
            float2 b3 = __half22float2(*(__half2*)&u3.y);
            acc.x += a0.x*w0 + a1.x*w1 + a2.x*w2 + a3.x*w3;
            acc.y += a0.y*w0 + a1.y*w1 + a2.y*w2 + a3.y*w3;
            acc.z += b0.x*w0 + b1.x*w1 + b2.x*w2 + b3.x*w3;
            acc.w += b0.y*w0 + b1.y*w1 + b2.y*w2 + b3.y*w3;
        }
        for (; p < pe; p++) {
            int s = col_idx[p];
            float w = dinv[s];
            uint2 us = base[(size_t)s * 32 + lane];
            float2 a = __half22float2(*(__half2*)&us.x);
            float2 b = __half22float2(*(__half2*)&us.y);
            acc.x += a.x*w; acc.y += a.y*w; acc.z += b.x*w; acc.w += b.y*w;
        }
        float4 b = ((const float4*)bias)[lane];
        float4 z;
        z.x = acc.x * di + b.x; z.y = acc.y * di + b.y;
        z.z = acc.z * di + b.z; z.w = acc.w * di + b.w;
        if (RELU) {
            z.x = fmaxf(z.x, 0.f); z.y = fmaxf(z.y, 0.f);
            z.z = fmaxf(z.z, 0.f); z.w = fmaxf(z.w, 0.f);
        }
        float4 a = ((const float4*)aw)[lane];
        float dot = z.x * a.x + z.y * a.y + z.z * a.z + z.w * a.w;
        #pragma unroll
        for (int off = 16; off > 0; off >>= 1)
            dot += __shfl_xor_sync(0xffffffffu, dot, off);
        float g = 1.0f / (1.0f + expf(-(dot + ab[0])));
        z.x *= g; z.y *= g; z.z *= g; z.w *= g;
        ((float4*)out)[(size_t)gw * 32 + lane] = z;
    } else {
        // C == 64: lane handles 2 channels (one half2, 4B load)
        const unsigned* base = (const unsigned*)h;   // 32 half2 per row
        unsigned u = base[(size_t)gw * 32 + lane];
        float2 ps = __half22float2(*(__half2*)&u);
        float2 acc = make_float2(ps.x * di, ps.y * di);

        int p = row_ptr[gw], pe = row_ptr[gw + 1];
        for (; p + 4 <= pe; p += 4) {
            int s0 = col_idx[p], s1 = col_idx[p+1], s2 = col_idx[p+2], s3 = col_idx[p+3];
            float w0 = dinv[s0], w1 = dinv[s1], w2 = dinv[s2], w3 = dinv[s3];
            unsigned u0 = base[(size_t)s0 * 32 + lane];
            unsigned u1 = base[(size_t)s1 * 32 + lane];
            unsigned u2 = base[(size_t)s2 * 32 + lane];
            unsigned u3 = base[(size_t)s3 * 32 + lane];
            float2 v0 = __half22float2(*(__half2*)&u0);
            float2 v1 = __half22float2(*(__half2*)&u1);
            float2 v2 = __half22float2(*(__half2*)&u2);
            float2 v3 = __half22float2(*(__half2*)&u3);
            acc.x += v0.x*w0 + v1.x*w1 + v2.x*w2 + v3.x*w3;
            acc.y += v0.y*w0 + v1.y*w1 + v2.y*w2 + v3.y*w3;
        }
        for (; p < pe; p++) {
            int s = col_idx[p];
            float w = dinv[s];
            unsigned us = base[(size_t)s * 32 + lane];
            float2 v = __half22float2(*(__half2*)&us);
            acc.x += v.x*w; acc.y += v.y*w;
        }
        float2 b = ((const float2*)bias)[lane];
        float2 z;
        z.x = acc.x * di + b.x; z.y = acc.y * di + b.y;
        if (RELU) { z.x = fmaxf(z.x, 0.f); z.y = fmaxf(z.y, 0.f); }
        float2 a = ((const float2*)aw)[lane];
        float dot = z.x * a.x + z.y * a.y;
        #pragma unroll
        for (int off = 16; off > 0; off >>= 1)
            dot += __shfl_xor_sync(0xffffffffu, dot, off);
        float g = 1.0f / (1.0f + expf(-(dot + ab[0])));
        z.x *= g; z.y *= g;
        ((float2*)out)[(size_t)gw * 32 + lane] = z;
    }
}

// ---------------- launch ----------------
extern "C" void kernel_launch(void* const* d_in, const int* in_sizes, int n_in,
                              void* d_out, int out_size) {
    const float* x    = (const float*)d_in[0];
    const void*  edge = d_in[1];
    const float* W1  = (const float*)d_in[2];
    const float* b1  = (const float*)d_in[3];
    const float* W2  = (const float*)d_in[4];
    const float* b2  = (const float*)d_in[5];
    const float* aw1 = (const float*)d_in[6];
    const float* ab1 = (const float*)d_in[7];
    const float* aw2 = (const float*)d_in[8];
    const float* ab2 = (const float*)d_in[9];
    float* out = (float*)d_out;

    float *dinv, *y1;
    __half *h1, *h2;
    int *cnt, *row_ptr, *fill, *col_idx, *blocksum;
    cudaGetSymbolAddress((void**)&dinv,     g_dinv);
    cudaGetSymbolAddress((void**)&h1,       g_h1);
    cudaGetSymbolAddress((void**)&y1,       g_y1);
    cudaGetSymbolAddress((void**)&h2,       g_h2);
    cudaGetSymbolAddress((void**)&cnt,      g_cnt);
    cudaGetSymbolAddress((void**)&row_ptr,  g_row_ptr);
    cudaGetSymbolAddress((void**)&fill,     g_fill);
    cudaGetSymbolAddress((void**)&col_idx,  g_col_idx);
    cudaGetSymbolAddress((void**)&blocksum, g_blocksum);

    static cudaStream_t s1 = nullptr;
    static cudaEvent_t evA = nullptr, evB = nullptr;
    if (s1 == nullptr) {
        cudaStreamCreateWithFlags(&s1, cudaStreamNonBlocking);
        cudaEventCreateWithFlags(&evA, cudaEventDisableTiming);
        cudaEventCreateWithFlags(&evB, cudaEventDisableTiming);
    }

    const int T = 256;

    // fork: full CSR chain (incl. dtype detect) on s1, GEMM1 on main stream
    cudaEventRecord(evA, 0);
    cudaStreamWaitEvent(s1, evA, 0);

    detect_edge_dtype_kernel<<<1, 32, 0, s1>>>(edge);
    zero_cnt_kernel<<<(N_NODES + T - 1) / T, T, 0, s1>>>(cnt);
    convert_edges_kernel<<<(2 * N_EDGES + T - 1) / T, T, 0, s1>>>(edge, cnt);
    scan_block_kernel<<<SCAN_BLOCKS, 1024, 0, s1>>>(cnt, row_ptr, dinv, blocksum);
    scan_tops_kernel<<<1, 64, 0, s1>>>(blocksum, row_ptr);
    scan_add_kernel<<<SCAN_BLOCKS, 1024, 0, s1>>>(row_ptr, blocksum, fill);
    fill_csr_kernel<<<(N_EDGES + T - 1) / T, T, 0, s1>>>(fill, col_idx);
    cudaEventRecord(evB, s1);

    // GEMM1 (independent of edges)
    {
        dim3 grid(DIM_HID / BN, (N_NODES + BM - 1) / BM);
        gemm_tf32_kernel<<<grid, 256>>>(x, W1, h1, N_NODES, DIM_IN, DIM_HID);
    }

    // join
    cudaStreamWaitEvent(0, evB, 0);

    gather_gate_kernel<DIM_HID, true><<<(N_NODES * 32 + T - 1) / T, T>>>(
        h1, row_ptr, col_idx, dinv, b1, aw1, ab1, y1);

    {
        dim3 grid(DIM_OUT / BN, (N_NODES + BM - 1) / BM);
        gemm_tf32_kernel<<<grid, 256>>>(y1, W2, h2, N_NODES, DIM_HID, DIM_OUT);
    }
    gather_gate_kernel<DIM_OUT, false><<<(N_NODES * 32 + T - 1) / T, T>>>(
        h2, row_ptr, col_idx, dinv, b2, aw2, ab2, out);
}

// round 8
// speedup vs baseline: 3.2748x; 1.0633x over previous
#include <cuda_runtime.h>
#include <cuda_fp16.h>
#include <math.h>

#define N_NODES 50000
#define N_EDGES 800000
#define DIM_IN  256
#define DIM_HID 128
#define DIM_OUT 64
#define SCAN_BLOCKS ((N_NODES + 1023) / 1024)   // 49

// ---------------- device scratch (no allocation allowed) ----------------
__device__ float  g_dinv[N_NODES];
__device__ __half g_h1[N_NODES * DIM_HID];   // GEMM1 out (fp16)
__device__ __half g_y1[N_NODES * DIM_HID];   // gather1 out (fp16, GEMM2 in)
__device__ __half g_h2[N_NODES * DIM_OUT];   // GEMM2 out (fp16)
__device__ int   g_src[N_EDGES];
__device__ int   g_dst[N_EDGES];
__device__ int   g_cnt[N_NODES];
__device__ int   g_row_ptr[N_NODES + 1];
__device__ int   g_fill[N_NODES];
__device__ int   g_col_idx[N_EDGES];
__device__ int   g_blocksum[64];
__device__ int   g_is64;

// ---------------- edge dtype detection ----------------
__global__ void detect_edge_dtype_kernel(const void* edge) {
    if (threadIdx.x == 0 && blockIdx.x == 0) {
        const long long* e64 = (const long long*)edge;
        int ok = 1;
        for (int i = 0; i < 16; i++) {
            long long v = e64[i];
            if (v < 0 || v >= (long long)N_NODES) { ok = 0; break; }
        }
        g_is64 = ok;
    }
}

__global__ void zero_cnt_kernel(int* cnt) {
    int i = blockIdx.x * blockDim.x + threadIdx.x;
    if (i < N_NODES) cnt[i] = 0;
}

__global__ void convert_edges_kernel(const void* edge, int* cnt) {
    int i = blockIdx.x * blockDim.x + threadIdx.x;
    if (i >= 2 * N_EDGES) return;
    int v;
    if (g_is64) v = (int)((const long long*)edge)[i];
    else        v = ((const int*)edge)[i];
    if (i < N_EDGES) g_src[i] = v;
    else {
        g_dst[i - N_EDGES] = v;
        atomicAdd(&cnt[v], 1);
    }
}

// ---------------- parallel 3-phase scan ----------------
__global__ __launch_bounds__(1024)
void scan_block_kernel(const int* __restrict__ cnt,
                       int* __restrict__ row_ptr,
                       float* __restrict__ dinv,
                       int* __restrict__ blocksum) {
    __shared__ int ws[32];
    const int t = threadIdx.x;
    const int lane = t & 31, w = t >> 5;
    const int i = blockIdx.x * 1024 + t;

    int val = (i < N_NODES) ? cnt[i] : 0;
    int v = val;
    #pragma unroll
    for (int off = 1; off < 32; off <<= 1) {
        int u = __shfl_up_sync(0xffffffffu, v, off);
        if (lane >= off) v += u;
    }
    if (lane == 31) ws[w] = v;
    __syncthreads();
    if (w == 0) {
        int x = ws[lane];
        #pragma unroll
        for (int off = 1; off < 32; off <<= 1) {
            int u = __shfl_up_sync(0xffffffffu, x, off);
            if (lane >= off) x += u;
        }
        ws[lane] = x;
    }
    __syncthreads();
    int incl = v + (w > 0 ? ws[w - 1] : 0);
    if (i < N_NODES) {
        row_ptr[i] = incl - val;
        dinv[i] = rsqrtf((float)val + 1.0f);
    }
    if (t == 1023) blocksum[blockIdx.x] = incl;
}

__global__ void scan_tops_kernel(int* __restrict__ blocksum, int* __restrict__ row_ptr) {
    __shared__ int wtot;
    const int t = threadIdx.x;   // 64 threads
    const int lane = t & 31, w = t >> 5;
    int val = (t < SCAN_BLOCKS) ? blocksum[t] : 0;
    int v = val;
    #pragma unroll
    for (int off = 1; off < 32; off <<= 1) {
        int u = __shfl_up_sync(0xffffffffu, v, off);
        if (lane >= off) v += u;
    }
    if (w == 0 && lane == 31) wtot = v;
    __syncthreads();
    if (w == 1) v += wtot;
    __syncthreads();
    if (t < SCAN_BLOCKS) blocksum[t] = v - val;
    if (t == SCAN_BLOCKS - 1) row_ptr[N_NODES] = v;
}

__global__ __launch_bounds__(1024)
void scan_add_kernel(int* __restrict__ row_ptr,
                     const int* __restrict__ blocksum,
                     int* __restrict__ fill) {
    const int i = blockIdx.x * 1024 + threadIdx.x;
    if (i < N_NODES) {
        int r = row_ptr[i] + blocksum[blockIdx.x];
        row_ptr[i] = r;
        fill[i] = r;
    }
}

__global__ void fill_csr_kernel(int* __restrict__ fill, int* __restrict__ col_idx) {
    int e = blockIdx.x * blockDim.x + threadIdx.x;
    if (e >= N_EDGES) return;
    int d = g_dst[e];
    int pos = atomicAdd(&fill[d], 1);
    col_idx[pos] = g_src[e];
}

// ---------------- tf32 helpers ----------------
__device__ __forceinline__ unsigned f2tf32(float f) {
    unsigned u;
    asm("cvt.rna.tf32.f32 %0, %1;" : "=r"(u) : "f"(f));
    return u;
}

// ---------------- tf32 GEMM (layer 1), register-staged double buffer ----------------
// H(fp16)[M,N] = A(fp32)[M,K] @ B(fp32)[K,N]
#define BM 128
#define BN 64
#define BK 32
#define AS_STRIDE 33
#define BS_STRIDE 68

__global__ __launch_bounds__(256)
void gemm_tf32_kernel(const float* __restrict__ A,
                      const float* __restrict__ B,
                      __half* __restrict__ H,
                      int M, int K, int N) {
    __shared__ unsigned As[BM * AS_STRIDE];
    __shared__ unsigned Bs[BK * BS_STRIDE];

    const int tid  = threadIdx.x;
    const int warp = tid >> 5;
    const int lane = tid & 31;
    const int wr = (warp & 3) * 32;
    const int wc = (warp >> 2) * 32;
    const int block_row = blockIdx.y * BM;
    const int block_col = blockIdx.x * BN;

    const int lq = lane >> 2;
    const int lr = lane & 3;

    // A-load addressing (fixed per thread)
    const int a_r  = tid >> 3;        // 0..31 base rows per chunk of 256
    const int a_c4 = tid & 7;
    const int b_r  = tid >> 4;
    const int b_c4 = tid & 15;

    float acc[2][4][4];
    #pragma unroll
    for (int mt = 0; mt < 2; mt++)
        #pragma unroll
        for (int nt = 0; nt < 4; nt++)
            #pragma unroll
            for (int i = 0; i < 4; i++) acc[mt][nt][i] = 0.0f;

    float4 rA[4];
    float4 rB[2];

    auto load_tile = [&](int k0) {
        #pragma unroll
        for (int l = 0; l < 4; l++) {
            int r  = a_r + l * 32;
            int gr = block_row + r;
            rA[l] = make_float4(0.f, 0.f, 0.f, 0.f);
            if (gr < M)
                rA[l] = *(const float4*)&A[(size_t)gr * K + k0 + a_c4 * 4];
        }
        #pragma unroll
        for (int l = 0; l < 2; l++) {
            int r = b_r + l * 16;
            rB[l] = *(const float4*)&B[(size_t)(k0 + r) * N + block_col + b_c4 * 4];
        }
    };

    auto store_tile = [&]() {
        #pragma unroll
        for (int l = 0; l < 4; l++) {
            int r = a_r + l * 32;
            unsigned* dst = &As[r * AS_STRIDE + a_c4 * 4];
            dst[0] = f2tf32(rA[l].x); dst[1] = f2tf32(rA[l].y);
            dst[2] = f2tf32(rA[l].z); dst[3] = f2tf32(rA[l].w);
        }
        #pragma unroll
        for (int l = 0; l < 2; l++) {
            int r = b_r + l * 16;
            unsigned* dst = &Bs[r * BS_STRIDE + b_c4 * 4];
            dst[0] = f2tf32(rB[l].x); dst[1] = f2tf32(rB[l].y);
            dst[2] = f2tf32(rB[l].z); dst[3] = f2tf32(rB[l].w);
        }
    };

    auto compute = [&]() {
        #pragma unroll
        for (int kk = 0; kk < BK; kk += 8) {
            unsigned a[2][4], b[4][2];
            #pragma unroll
            for (int mt = 0; mt < 2; mt++) {
                int r1 = wr + mt * 16 + lq;
                a[mt][0] = As[r1 * AS_STRIDE + kk + lr];
                a[mt][1] = As[(r1 + 8) * AS_STRIDE + kk + lr];
                a[mt][2] = As[r1 * AS_STRIDE + kk + lr + 4];
                a[mt][3] = As[(r1 + 8) * AS_STRIDE + kk + lr + 4];
            }
            #pragma unroll
            for (int nt = 0; nt < 4; nt++) {
                int c = wc + nt * 8 + lq;
                b[nt][0] = Bs[(kk + lr) * BS_STRIDE + c];
                b[nt][1] = Bs[(kk + lr + 4) * BS_STRIDE + c];
            }
            #pragma unroll
            for (int mt = 0; mt < 2; mt++)
                #pragma unroll
                for (int nt = 0; nt < 4; nt++) {
                    asm volatile(
                        "mma.sync.aligned.m16n8k8.row.col.f32.tf32.tf32.f32 "
                        "{%0,%1,%2,%3}, {%4,%5,%6,%7}, {%8,%9}, {%0,%1,%2,%3};"
                        : "+f"(acc[mt][nt][0]), "+f"(acc[mt][nt][1]),
                          "+f"(acc[mt][nt][2]), "+f"(acc[mt][nt][3])
                        : "r"(a[mt][0]), "r"(a[mt][1]), "r"(a[mt][2]), "r"(a[mt][3]),
                          "r"(b[nt][0]), "r"(b[nt][1]));
                }
        }
    };

    // prologue
    load_tile(0);
    store_tile();
    __syncthreads();

    for (int k0 = BK; k0 < K; k0 += BK) {
        load_tile(k0);     // LDG in flight during compute
        compute();
        __syncthreads();
        store_tile();
        __syncthreads();
    }
    compute();

    // epilogue: pack pairs to half2 and store
    #pragma unroll
    for (int mt = 0; mt < 2; mt++) {
        int r0 = block_row + wr + mt * 16 + lq;
        int r1 = r0 + 8;
        #pragma unroll
        for (int nt = 0; nt < 4; nt++) {
            int c = block_col + wc + nt * 8 + lr * 2;
            if (r0 < M)
                *(__half2*)&H[(size_t)r0 * N + c] = __floats2half2_rn(acc[mt][nt][0], acc[mt][nt][1]);
            if (r1 < M)
                *(__half2*)&H[(size_t)r1 * N + c] = __floats2half2_rn(acc[mt][nt][2], acc[mt][nt][3]);
        }
    }
}

// ---------------- fp16 GEMM (layer 2): H(fp16)[M,64] = A(fp16)[M,128] @ W2(fp32->fp16) ----------------
// 128x64 block, 8 warps 4x2, warp tile 32x32 = 2x4 m16n8k16; K in 2 chunks of 64.
#define BK2 64
#define AS2_STRIDE 72   // halves; 36 words -> bank (4g+lr) conflict-free
#define BS2_STRIDE 72

__global__ __launch_bounds__(256)
void gemm_fp16_kernel(const __half* __restrict__ A,
                      const float* __restrict__ B,   // W2 [128,64] fp32
                      __half* __restrict__ H,
                      int M) {
    __shared__ __half As[BM * AS2_STRIDE];       // [row][k-chunk]
    __shared__ __half Bs2[DIM_OUT * BS2_STRIDE]; // [n][k-chunk] (transposed)

    const int tid  = threadIdx.x;
    const int warp = tid >> 5;
    const int lane = tid & 31;
    const int wr = (warp & 3) * 32;
    const int wc = (warp >> 2) * 32;
    const int block_row = blockIdx.x * BM;

    const int lq = lane >> 2;
    const int lr = lane & 3;

    float acc[2][4][4];
    #pragma unroll
    for (int mt = 0; mt < 2; mt++)
        #pragma unroll
        for (int nt = 0; nt < 4; nt++)
            #pragma unroll
            for (int i = 0; i < 4; i++) acc[mt][nt][i] = 0.0f;

    for (int k0 = 0; k0 < DIM_HID; k0 += BK2) {
        // A tile: 128 rows x 64 halves = 1024 uint4, 4 per thread
        #pragma unroll
        for (int l = 0; l < 4; l++) {
            int idx = tid + l * 256;
            int r  = idx >> 3;
            int c8 = idx & 7;
            int gr = block_row + r;
            uint4 v = make_uint4(0u, 0u, 0u, 0u);
            if (gr < M)
                v = *(const uint4*)&A[(size_t)gr * DIM_HID + k0 + c8 * 8];
            *(uint4*)&As[r * AS2_STRIDE + c8 * 8] = v;
        }
        // B tile: W2 rows k0..k0+63, cols 0..63 -> Bs2[n][k]
        #pragma unroll
        for (int l = 0; l < 16; l++) {
            int idx = tid + l * 256;
            int k = idx >> 6;
            int n = idx & 63;
            Bs2[n * BS2_STRIDE + k] = __float2half_rn(B[(size_t)(k0 + k) * DIM_OUT + n]);
        }
        __syncthreads();

        #pragma unroll
        for (int kk = 0; kk < BK2; kk += 16) {
            unsigned a[2][4], b[4][2];
            #pragma unroll
            for (int mt = 0; mt < 2; mt++) {
                int r1 = wr + mt * 16 + lq;
                a[mt][0] = *(const unsigned*)&As[r1 * AS2_STRIDE + kk + lr * 2];
                a[mt][1] = *(const unsigned*)&As[(r1 + 8) * AS2_STRIDE + kk + lr * 2];
                a[mt][2] = *(const unsigned*)&As[r1 * AS2_STRIDE + kk + lr * 2 + 8];
                a[mt][3] = *(const unsigned*)&As[(r1 + 8) * AS2_STRIDE + kk + lr * 2 + 8];
            }
            #pragma unroll
            for (int nt = 0; nt < 4; nt++) {
                int c = wc + nt * 8 + lq;
                b[nt][0] = *(const unsigned*)&Bs2[c * BS2_STRIDE + kk + lr * 2];
                b[nt][1] = *(const unsigned*)&Bs2[c * BS2_STRIDE + kk + lr * 2 + 8];
            }
            #pragma unroll
            for (int mt = 0; mt < 2; mt++)
                #pragma unroll
                for (int nt = 0; nt < 4; nt++) {
                    asm volatile(
                        "mma.sync.aligned.m16n8k16.row.col.f32.f16.f16.f32 "
                        "{%0,%1,%2,%3}, {%4,%5,%6,%7}, {%8,%9}, {%0,%1,%2,%3};"
                        : "+f"(acc[mt][nt][0]), "+f"(acc[mt][nt][1]),
                          "+f"(acc[mt][nt][2]), "+f"(acc[mt][nt][3])
                        : "r"(a[mt][0]), "r"(a[mt][1]), "r"(a[mt][2]), "r"(a[mt][3]),
                          "r"(b[nt][0]), "r"(b[nt][1]));
                }
        }
        __syncthreads();
    }

    #pragma unroll
    for (int mt = 0; mt < 2; mt++) {
        int r0 = block_row + wr + mt * 16 + lq;
        int r1 = r0 + 8;
        #pragma unroll
        for (int nt = 0; nt < 4; nt++) {
            int c = wc + nt * 8 + lr * 2;
            if (r0 < M)
                *(__half2*)&H[(size_t)r0 * DIM_OUT + c] = __floats2half2_rn(acc[mt][nt][0], acc[mt][nt][1]);
            if (r1 < M)
                *(__half2*)&H[(size_t)r1 * DIM_OUT + c] = __floats2half2_rn(acc[mt][nt][2], acc[mt][nt][3]);
        }
    }
}

// ---------------- fused CSR gather (fp16 in) + bias + (relu) + gate ----------------
// acc = dinv[n]*h[n] + sum_s dinv[s]*h[s];  z = [relu](acc*dinv[n] + b);
// out = z * sigmoid(z . aw + ab).  OUT_HALF selects fp16 vs fp32 output.
template<int C, bool RELU, bool OUT_HALF>
__global__ void gather_gate_kernel(const __half* __restrict__ h,
                                   const int* __restrict__ row_ptr,
                                   const int* __restrict__ col_idx,
                                   const float* __restrict__ dinv,
                                   const float* __restrict__ bias,
                                   const float* __restrict__ aw,
                                   const float* __restrict__ ab,
                                   void* __restrict__ out) {
    int gw   = (blockIdx.x * blockDim.x + threadIdx.x) >> 5;
    int lane = threadIdx.x & 31;
    if (gw >= N_NODES) return;

    float di = dinv[gw];

    if constexpr (C == 128) {
        const uint2* base = (const uint2*)h;   // 32 uint2 per row
        uint2 u = base[(size_t)gw * 32 + lane];
        float2 p0 = __half22float2(*(__half2*)&u.x);
        float2 p1 = __half22float2(*(__half2*)&u.y);
        float4 acc = make_float4(p0.x * di, p0.y * di, p1.x * di, p1.y * di);

        int p = row_ptr[gw], pe = row_ptr[gw + 1];
        for (; p + 8 <= pe; p += 8) {
            int   si[8]; float wi[8]; uint2 ui[8];
            #pragma unroll
            for (int q = 0; q < 8; q++) si[q] = col_idx[p + q];
            #pragma unroll
            for (int q = 0; q < 8; q++) wi[q] = dinv[si[q]];
            #pragma unroll
            for (int q = 0; q < 8; q++) ui[q] = base[(size_t)si[q] * 32 + lane];
            #pragma unroll
            for (int q = 0; q < 8; q++) {
                float2 a = __half22float2(*(__half2*)&ui[q].x);
                float2 b = __half22float2(*(__half2*)&ui[q].y);
                acc.x += a.x * wi[q]; acc.y += a.y * wi[q];
                acc.z += b.x * wi[q]; acc.w += b.y * wi[q];
            }
        }
        for (; p < pe; p++) {
            int s = col_idx[p];
            float w = dinv[s];
            uint2 us = base[(size_t)s * 32 + lane];
            float2 a = __half22float2(*(__half2*)&us.x);
            float2 b = __half22float2(*(__half2*)&us.y);
            acc.x += a.x*w; acc.y += a.y*w; acc.z += b.x*w; acc.w += b.y*w;
        }
        float4 b = ((const float4*)bias)[lane];
        float4 z;
        z.x = acc.x * di + b.x; z.y = acc.y * di + b.y;
        z.z = acc.z * di + b.z; z.w = acc.w * di + b.w;
        if (RELU) {
            z.x = fmaxf(z.x, 0.f); z.y = fmaxf(z.y, 0.f);
            z.z = fmaxf(z.z, 0.f); z.w = fmaxf(z.w, 0.f);
        }
        float4 a = ((const float4*)aw)[lane];
        float dot = z.x * a.x + z.y * a.y + z.z * a.z + z.w * a.w;
        #pragma unroll
        for (int off = 16; off > 0; off >>= 1)
            dot += __shfl_xor_sync(0xffffffffu, dot, off);
        float g = 1.0f / (1.0f + expf(-(dot + ab[0])));
        z.x *= g; z.y *= g; z.z *= g; z.w *= g;
        if constexpr (OUT_HALF) {
            __half2 z01 = __floats2half2_rn(z.x, z.y);
            __half2 z23 = __floats2half2_rn(z.z, z.w);
            uint2 uo;
            uo.x = *(unsigned*)&z01; uo.y = *(unsigned*)&z23;
            ((uint2*)out)[(size_t)gw * 32 + lane] = uo;
        } else {
            ((float4*)out)[(size_t)gw * 32 + lane] = z;
        }
    } else {
        const unsigned* base = (const unsigned*)h;   // 32 half2 per row
        unsigned u = base[(size_t)gw * 32 + lane];
        float2 ps = __half22float2(*(__half2*)&u);
        float2 acc = make_float2(ps.x * di, ps.y * di);

        int p = row_ptr[gw], pe = row_ptr[gw + 1];
        for (; p + 8 <= pe; p += 8) {
            int si[8]; float wi[8]; unsigned ui[8];
            #pragma unroll
            for (int q = 0; q < 8; q++) si[q] = col_idx[p + q];
            #pragma unroll
            for (int q = 0; q < 8; q++) wi[q] = dinv[si[q]];
            #pragma unroll
            for (int q = 0; q < 8; q++) ui[q] = base[(size_t)si[q] * 32 + lane];
            #pragma unroll
            for (int q = 0; q < 8; q++) {
                float2 v = __half22float2(*(__half2*)&ui[q]);
                acc.x += v.x * wi[q]; acc.y += v.y * wi[q];
            }
        }
        for (; p < pe; p++) {
            int s = col_idx[p];
            float w = dinv[s];
            unsigned us = base[(size_t)s * 32 + lane];
            float2 v = __half22float2(*(__half2*)&us);
            acc.x += v.x*w; acc.y += v.y*w;
        }
        float2 b = ((const float2*)bias)[lane];
        float2 z;
        z.x = acc.x * di + b.x; z.y = acc.y * di + b.y;
        if (RELU) { z.x = fmaxf(z.x, 0.f); z.y = fmaxf(z.y, 0.f); }
        float2 a = ((const float2*)aw)[lane];
        float dot = z.x * a.x + z.y * a.y;
        #pragma unroll
        for (int off = 16; off > 0; off >>= 1)
            dot += __shfl_xor_sync(0xffffffffu, dot, off);
        float g = 1.0f / (1.0f + expf(-(dot + ab[0])));
        z.x *= g; z.y *= g;
        if constexpr (OUT_HALF) {
            __half2 zo = __floats2half2_rn(z.x, z.y);
            ((unsigned*)out)[(size_t)gw * 32 + lane] = *(unsigned*)&zo;
        } else {
            ((float2*)out)[(size_t)gw * 32 + lane] = z;
        }
    }
}

// ---------------- launch ----------------
extern "C" void kernel_launch(void* const* d_in, const int* in_sizes, int n_in,
                              void* d_out, int out_size) {
    const float* x    = (const float*)d_in[0];
    const void*  edge = d_in[1];
    const float* W1  = (const float*)d_in[2];
    const float* b1  = (const float*)d_in[3];
    const float* W2  = (const float*)d_in[4];
    const float* b2  = (const float*)d_in[5];
    const float* aw1 = (const float*)d_in[6];
    const float* ab1 = (const float*)d_in[7];
    const float* aw2 = (const float*)d_in[8];
    const float* ab2 = (const float*)d_in[9];
    float* out = (float*)d_out;

    float *dinv;
    __half *h1, *y1, *h2;
    int *cnt, *row_ptr, *fill, *col_idx, *blocksum;
    cudaGetSymbolAddress((void**)&dinv,     g_dinv);
    cudaGetSymbolAddress((void**)&h1,       g_h1);
    cudaGetSymbolAddress((void**)&y1,       g_y1);
    cudaGetSymbolAddress((void**)&h2,       g_h2);
    cudaGetSymbolAddress((void**)&cnt,      g_cnt);
    cudaGetSymbolAddress((void**)&row_ptr,  g_row_ptr);
    cudaGetSymbolAddress((void**)&fill,     g_fill);
    cudaGetSymbolAddress((void**)&col_idx,  g_col_idx);
    cudaGetSymbolAddress((void**)&blocksum, g_blocksum);

    static cudaStream_t s1 = nullptr;
    static cudaEvent_t evA = nullptr, evB = nullptr;
    if (s1 == nullptr) {
        cudaStreamCreateWithFlags(&s1, cudaStreamNonBlocking);
        cudaEventCreateWithFlags(&evA, cudaEventDisableTiming);
        cudaEventCreateWithFlags(&evB, cudaEventDisableTiming);
    }

    const int T = 256;

    // fork: full CSR chain on s1, GEMM1 on main stream
    cudaEventRecord(evA, 0);
    cudaStreamWaitEvent(s1, evA, 0);

    detect_edge_dtype_kernel<<<1, 32, 0, s1>>>(edge);
    zero_cnt_kernel<<<(N_NODES + T - 1) / T, T, 0, s1>>>(cnt);
    convert_edges_kernel<<<(2 * N_EDGES + T - 1) / T, T, 0, s1>>>(edge, cnt);
    scan_block_kernel<<<SCAN_BLOCKS, 1024, 0, s1>>>(cnt, row_ptr, dinv, blocksum);
    scan_tops_kernel<<<1, 64, 0, s1>>>(blocksum, row_ptr);
    scan_add_kernel<<<SCAN_BLOCKS, 1024, 0, s1>>>(row_ptr, blocksum, fill);
    fill_csr_kernel<<<(N_EDGES + T - 1) / T, T, 0, s1>>>(fill, col_idx);
    cudaEventRecord(evB, s1);

    // GEMM1 (independent of edges)
    {
        dim3 grid(DIM_HID / BN, (N_NODES + BM - 1) / BM);
        gemm_tf32_kernel<<<grid, 256>>>(x, W1, h1, N_NODES, DIM_IN, DIM_HID);
    }

    // join
    cudaStreamWaitEvent(0, evB, 0);

    gather_gate_kernel<DIM_HID, true, true><<<(N_NODES * 32 + T - 1) / T, T>>>(
        h1, row_ptr, col_idx, dinv, b1, aw1, ab1, y1);

    gemm_fp16_kernel<<<(N_NODES + BM - 1) / BM, 256>>>(y1, W2, h2, N_NODES);

    gather_gate_kernel<DIM_OUT, false, false><<<(N_NODES * 32 + T - 1) / T, T>>>(
        h2, row_ptr, col_idx, dinv, b2, aw2, ab2, out);
}

// round 9
// speedup vs baseline: 3.6905x; 1.1269x over previous
#include <cuda_runtime.h>
#include <cuda_fp16.h>
#include <math.h>

#define N_NODES 50000
#define N_EDGES 800000
#define DIM_IN  256
#define DIM_HID 128
#define DIM_OUT 64
#define SCAN_BLOCKS ((N_NODES + 1023) / 1024)   // 49

// ---------------- device scratch (no allocation allowed) ----------------
__device__ float  g_dinv[N_NODES];
__device__ __half g_h1[N_NODES * DIM_HID];   // GEMM1 out (fp16)
__device__ __half g_y1[N_NODES * DIM_HID];   // gather1 out (fp16, GEMM2 in)
__device__ __half g_h2[N_NODES * DIM_OUT];   // GEMM2 out (fp16)
__device__ int   g_src[N_EDGES];
__device__ int   g_dst[N_EDGES];
__device__ int   g_cnt[N_NODES];
__device__ int   g_row_ptr[N_NODES + 1];
__device__ int   g_fill[N_NODES];
__device__ int   g_col_idx[N_EDGES];
__device__ int   g_blocksum[64];
__device__ int   g_is64;

// ---------------- edge dtype detection ----------------
__global__ void detect_edge_dtype_kernel(const void* edge) {
    if (threadIdx.x == 0 && blockIdx.x == 0) {
        const long long* e64 = (const long long*)edge;
        int ok = 1;
        for (int i = 0; i < 16; i++) {
            long long v = e64[i];
            if (v < 0 || v >= (long long)N_NODES) { ok = 0; break; }
        }
        g_is64 = ok;
    }
}

__global__ void zero_cnt_kernel(int* cnt) {
    int i = blockIdx.x * blockDim.x + threadIdx.x;
    if (i < N_NODES) cnt[i] = 0;
}

__global__ void convert_edges_kernel(const void* edge, int* cnt) {
    int i = blockIdx.x * blockDim.x + threadIdx.x;
    if (i >= 2 * N_EDGES) return;
    int v;
    if (g_is64) v = (int)((const long long*)edge)[i];
    else        v = ((const int*)edge)[i];
    if (i < N_EDGES) g_src[i] = v;
    else {
        g_dst[i - N_EDGES] = v;
        atomicAdd(&cnt[v], 1);
    }
}

// ---------------- parallel 3-phase scan ----------------
__global__ __launch_bounds__(1024)
void scan_block_kernel(const int* __restrict__ cnt,
                       int* __restrict__ row_ptr,
                       float* __restrict__ dinv,
                       int* __restrict__ blocksum) {
    __shared__ int ws[32];
    const int t = threadIdx.x;
    const int lane = t & 31, w = t >> 5;
    const int i = blockIdx.x * 1024 + t;

    int val = (i < N_NODES) ? cnt[i] : 0;
    int v = val;
    #pragma unroll
    for (int off = 1; off < 32; off <<= 1) {
        int u = __shfl_up_sync(0xffffffffu, v, off);
        if (lane >= off) v += u;
    }
    if (lane == 31) ws[w] = v;
    __syncthreads();
    if (w == 0) {
        int x = ws[lane];
        #pragma unroll
        for (int off = 1; off < 32; off <<= 1) {
            int u = __shfl_up_sync(0xffffffffu, x, off);
            if (lane >= off) x += u;
        }
        ws[lane] = x;
    }
    __syncthreads();
    int incl = v + (w > 0 ? ws[w - 1] : 0);
    if (i < N_NODES) {
        row_ptr[i] = incl - val;
        dinv[i] = rsqrtf((float)val + 1.0f);
    }
    if (t == 1023) blocksum[blockIdx.x] = incl;
}

__global__ void scan_tops_kernel(int* __restrict__ blocksum, int* __restrict__ row_ptr) {
    __shared__ int wtot;
    const int t = threadIdx.x;   // 64 threads
    const int lane = t & 31, w = t >> 5;
    int val = (t < SCAN_BLOCKS) ? blocksum[t] : 0;
    int v = val;
    #pragma unroll
    for (int off = 1; off < 32; off <<= 1) {
        int u = __shfl_up_sync(0xffffffffu, v, off);
        if (lane >= off) v += u;
    }
    if (w == 0 && lane == 31) wtot = v;
    __syncthreads();
    if (w == 1) v += wtot;
    __syncthreads();
    if (t < SCAN_BLOCKS) blocksum[t] = v - val;
    if (t == SCAN_BLOCKS - 1) row_ptr[N_NODES] = v;
}

__global__ __launch_bounds__(1024)
void scan_add_kernel(int* __restrict__ row_ptr,
                     const int* __restrict__ blocksum,
                     int* __restrict__ fill) {
    const int i = blockIdx.x * 1024 + threadIdx.x;
    if (i < N_NODES) {
        int r = row_ptr[i] + blocksum[blockIdx.x];
        row_ptr[i] = r;
        fill[i] = r;
    }
}

__global__ void fill_csr_kernel(int* __restrict__ fill, int* __restrict__ col_idx) {
    int e = blockIdx.x * blockDim.x + threadIdx.x;
    if (e >= N_EDGES) return;
    int d = g_dst[e];
    int pos = atomicAdd(&fill[d], 1);
    col_idx[pos] = g_src[e];
}

// ---------------- unified fp16 tensor-core GEMM ----------------
// H(fp16)[M,N] = A[M,K] @ B(fp32)[K,N]
// A_FP16=false: A is fp32, converted to fp16 in the load stage (layer 1)
// A_FP16=true : A is fp16, loaded directly (layer 2)
// Block 128x64, BK=64, 8 warps 4(M)x2(N), warp tile 32x32 = 2x4 m16n8k16.
// Register-staged double buffering on global loads.
#define BM 128
#define BN 64
#define BKH 64
#define ASH_STRIDE 72   // halves; bank = (4*lq + lr) % 32 -> conflict-free
#define BSH_STRIDE 72

template<bool A_FP16>
__global__ __launch_bounds__(256)
void gemm_half_kernel(const void* __restrict__ Av,
                      const float* __restrict__ B,
                      __half* __restrict__ H,
                      int M, int K, int N) {
    __shared__ __half As[BM * ASH_STRIDE];      // [row][k]
    __shared__ __half Bs[BN * BSH_STRIDE];      // [n][k] (transposed)

    const int tid  = threadIdx.x;
    const int warp = tid >> 5;
    const int lane = tid & 31;
    const int wr = (warp & 3) * 32;
    const int wc = (warp >> 2) * 32;
    const int block_row = blockIdx.y * BM;
    const int block_col = blockIdx.x * BN;

    const int lq = lane >> 2;
    const int lr = lane & 3;

    float acc[2][4][4];
    #pragma unroll
    for (int mt = 0; mt < 2; mt++)
        #pragma unroll
        for (int nt = 0; nt < 4; nt++)
            #pragma unroll
            for (int i = 0; i < 4; i++) acc[mt][nt][i] = 0.0f;

    // staging registers
    float4 rA32[8];   // layer1: 128x64 fp32 = 2048 float4 / 256 thr = 8
    uint4  rA16[4];   // layer2: 128x64 fp16 = 1024 uint4  / 256 thr = 4
    float  rB[16];    // 64x64 fp32 = 4096 / 256 = 16

    auto load_tile = [&](int k0) {
        if constexpr (!A_FP16) {
            const float* A = (const float*)Av;
            #pragma unroll
            for (int l = 0; l < 8; l++) {
                int idx = tid + l * 256;
                int r  = idx >> 4;         // 16 float4 per row
                int c4 = idx & 15;
                int gr = block_row + r;
                rA32[l] = make_float4(0.f, 0.f, 0.f, 0.f);
                if (gr < M)
                    rA32[l] = *(const float4*)&A[(size_t)gr * K + k0 + c4 * 4];
            }
        } else {
            const __half* A = (const __half*)Av;
            #pragma unroll
            for (int l = 0; l < 4; l++) {
                int idx = tid + l * 256;
                int r  = idx >> 3;         // 8 uint4 per row
                int c8 = idx & 7;
                int gr = block_row + r;
                rA16[l] = make_uint4(0u, 0u, 0u, 0u);
                if (gr < M)
                    rA16[l] = *(const uint4*)&A[(size_t)gr * K + k0 + c8 * 8];
            }
        }
        #pragma unroll
        for (int l = 0; l < 16; l++) {
            int idx = tid + l * 256;
            int k = idx >> 6;
            int n = idx & 63;
            rB[l] = B[(size_t)(k0 + k) * N + block_col + n];
        }
    };

    auto store_tile = [&]() {
        if constexpr (!A_FP16) {
            #pragma unroll
            for (int l = 0; l < 8; l++) {
                int idx = tid + l * 256;
                int r  = idx >> 4;
                int c4 = idx & 15;
                __half2 h01 = __floats2half2_rn(rA32[l].x, rA32[l].y);
                __half2 h23 = __floats2half2_rn(rA32[l].z, rA32[l].w);
                uint2 u;
                u.x = *(unsigned*)&h01; u.y = *(unsigned*)&h23;
                *(uint2*)&As[r * ASH_STRIDE + c4 * 4] = u;
            }
        } else {
            #pragma unroll
            for (int l = 0; l < 4; l++) {
                int idx = tid + l * 256;
                int r  = idx >> 3;
                int c8 = idx & 7;
                *(uint4*)&As[r * ASH_STRIDE + c8 * 8] = rA16[l];
            }
        }
        #pragma unroll
        for (int l = 0; l < 16; l++) {
            int idx = tid + l * 256;
            int k = idx >> 6;
            int n = idx & 63;
            Bs[n * BSH_STRIDE + k] = __float2half_rn(rB[l]);
        }
    };

    auto compute = [&]() {
        #pragma unroll
        for (int kk = 0; kk < BKH; kk += 16) {
            unsigned a[2][4], b[4][2];
            #pragma unroll
            for (int mt = 0; mt < 2; mt++) {
                int r1 = wr + mt * 16 + lq;
                a[mt][0] = *(const unsigned*)&As[r1 * ASH_STRIDE + kk + lr * 2];
                a[mt][1] = *(const unsigned*)&As[(r1 + 8) * ASH_STRIDE + kk + lr * 2];
                a[mt][2] = *(const unsigned*)&As[r1 * ASH_STRIDE + kk + lr * 2 + 8];
                a[mt][3] = *(const unsigned*)&As[(r1 + 8) * ASH_STRIDE + kk + lr * 2 + 8];
            }
            #pragma unroll
            for (int nt = 0; nt < 4; nt++) {
                int c = wc + nt * 8 + lq;
                b[nt][0] = *(const unsigned*)&Bs[c * BSH_STRIDE + kk + lr * 2];
                b[nt][1] = *(const unsigned*)&Bs[c * BSH_STRIDE + kk + lr * 2 + 8];
            }
            #pragma unroll
            for (int mt = 0; mt < 2; mt++)
                #pragma unroll
                for (int nt = 0; nt < 4; nt++) {
                    asm volatile(
                        "mma.sync.aligned.m16n8k16.row.col.f32.f16.f16.f32 "
                        "{%0,%1,%2,%3}, {%4,%5,%6,%7}, {%8,%9}, {%0,%1,%2,%3};"
                        : "+f"(acc[mt][nt][0]), "+f"(acc[mt][nt][1]),
                          "+f"(acc[mt][nt][2]), "+f"(acc[mt][nt][3])
                        : "r"(a[mt][0]), "r"(a[mt][1]), "r"(a[mt][2]), "r"(a[mt][3]),
                          "r"(b[nt][0]), "r"(b[nt][1]));
                }
        }
    };

    // prologue
    load_tile(0);
    store_tile();
    __syncthreads();

    for (int k0 = BKH; k0 < K; k0 += BKH) {
        load_tile(k0);     // LDG in flight during compute
        compute();
        __syncthreads();
        store_tile();
        __syncthreads();
    }
    compute();

    // epilogue: pack pairs to half2 and store
    #pragma unroll
    for (int mt = 0; mt < 2; mt++) {
        int r0 = block_row + wr + mt * 16 + lq;
        int r1 = r0 + 8;
        #pragma unroll
        for (int nt = 0; nt < 4; nt++) {
            int c = block_col + wc + nt * 8 + lr * 2;
            if (r0 < M)
                *(__half2*)&H[(size_t)r0 * N + c] = __floats2half2_rn(acc[mt][nt][0], acc[mt][nt][1]);
            if (r1 < M)
                *(__half2*)&H[(size_t)r1 * N + c] = __floats2half2_rn(acc[mt][nt][2], acc[mt][nt][3]);
        }
    }
}

// ---------------- fused CSR gather (fp16 in) + bias + (relu) + gate ----------------
template<int C, bool RELU, bool OUT_HALF>
__global__ void gather_gate_kernel(const __half* __restrict__ h,
                                   const int* __restrict__ row_ptr,
                                   const int* __restrict__ col_idx,
                                   const float* __restrict__ dinv,
                                   const float* __restrict__ bias,
                                   const float* __restrict__ aw,
                                   const float* __restrict__ ab,
                                   void* __restrict__ out) {
    int gw   = (blockIdx.x * blockDim.x + threadIdx.x) >> 5;
    int lane = threadIdx.x & 31;
    if (gw >= N_NODES) return;

    float di = dinv[gw];

    if constexpr (C == 128) {
        const uint2* base = (const uint2*)h;
        uint2 u = base[(size_t)gw * 32 + lane];
        float2 p0 = __half22float2(*(__half2*)&u.x);
        float2 p1 = __half22float2(*(__half2*)&u.y);
        float4 acc = make_float4(p0.x * di, p0.y * di, p1.x * di, p1.y * di);

        int p = row_ptr[gw], pe = row_ptr[gw + 1];
        for (; p + 8 <= pe; p += 8) {
            int   si[8]; float wi[8]; uint2 ui[8];
            #pragma unroll
            for (int q = 0; q < 8; q++) si[q] = col_idx[p + q];
            #pragma unroll
            for (int q = 0; q < 8; q++) wi[q] = dinv[si[q]];
            #pragma unroll
            for (int q = 0; q < 8; q++) ui[q] = base[(size_t)si[q] * 32 + lane];
            #pragma unroll
            for (int q = 0; q < 8; q++) {
                float2 a = __half22float2(*(__half2*)&ui[q].x);
                float2 b = __half22float2(*(__half2*)&ui[q].y);
                acc.x += a.x * wi[q]; acc.y += a.y * wi[q];
                acc.z += b.x * wi[q]; acc.w += b.y * wi[q];
            }
        }
        for (; p < pe; p++) {
            int s = col_idx[p];
            float w = dinv[s];
            uint2 us = base[(size_t)s * 32 + lane];
            float2 a = __half22float2(*(__half2*)&us.x);
            float2 b = __half22float2(*(__half2*)&us.y);
            acc.x += a.x*w; acc.y += a.y*w; acc.z += b.x*w; acc.w += b.y*w;
        }
        float4 b = ((const float4*)bias)[lane];
        float4 z;
        z.x = acc.x * di + b.x; z.y = acc.y * di + b.y;
        z.z = acc.z * di + b.z; z.w = acc.w * di + b.w;
        if (RELU) {
            z.x = fmaxf(z.x, 0.f); z.y = fmaxf(z.y, 0.f);
            z.z = fmaxf(z.z, 0.f); z.w = fmaxf(z.w, 0.f);
        }
        float4 a = ((const float4*)aw)[lane];
        float dot = z.x * a.x + z.y * a.y + z.z * a.z + z.w * a.w;
        #pragma unroll
        for (int off = 16; off > 0; off >>= 1)
            dot += __shfl_xor_sync(0xffffffffu, dot, off);
        float g = 1.0f / (1.0f + expf(-(dot + ab[0])));
        z.x *= g; z.y *= g; z.z *= g; z.w *= g;
        if constexpr (OUT_HALF) {
            __half2 z01 = __floats2half2_rn(z.x, z.y);
            __half2 z23 = __floats2half2_rn(z.z, z.w);
            uint2 uo;
            uo.x = *(unsigned*)&z01; uo.y = *(unsigned*)&z23;
            ((uint2*)out)[(size_t)gw * 32 + lane] = uo;
        } else {
            ((float4*)out)[(size_t)gw * 32 + lane] = z;
        }
    } else {
        const unsigned* base = (const unsigned*)h;
        unsigned u = base[(size_t)gw * 32 + lane];
        float2 ps = __half22float2(*(__half2*)&u);
        float2 acc = make_float2(ps.x * di, ps.y * di);

        int p = row_ptr[gw], pe = row_ptr[gw + 1];
        for (; p + 8 <= pe; p += 8) {
            int si[8]; float wi[8]; unsigned ui[8];
            #pragma unroll
            for (int q = 0; q < 8; q++) si[q] = col_idx[p + q];
            #pragma unroll
            for (int q = 0; q < 8; q++) wi[q] = dinv[si[q]];
            #pragma unroll
            for (int q = 0; q < 8; q++) ui[q] = base[(size_t)si[q] * 32 + lane];
            #pragma unroll
            for (int q = 0; q < 8; q++) {
                float2 v = __half22float2(*(__half2*)&ui[q]);
                acc.x += v.x * wi[q]; acc.y += v.y * wi[q];
            }
        }
        for (; p < pe; p++) {
            int s = col_idx[p];
            float w = dinv[s];
            unsigned us = base[(size_t)s * 32 + lane];
            float2 v = __half22float2(*(__half2*)&us);
            acc.x += v.x*w; acc.y += v.y*w;
        }
        float2 b = ((const float2*)bias)[lane];
        float2 z;
        z.x = acc.x * di + b.x; z.y = acc.y * di + b.y;
        if (RELU) { z.x = fmaxf(z.x, 0.f); z.y = fmaxf(z.y, 0.f); }
        float2 a = ((const float2*)aw)[lane];
        float dot = z.x * a.x + z.y * a.y;
        #pragma unroll
        for (int off = 16; off > 0; off >>= 1)
            dot += __shfl_xor_sync(0xffffffffu, dot, off);
        float g = 1.0f / (1.0f + expf(-(dot + ab[0])));
        z.x *= g; z.y *= g;
        if constexpr (OUT_HALF) {
            __half2 zo = __floats2half2_rn(z.x, z.y);
            ((unsigned*)out)[(size_t)gw * 32 + lane] = *(unsigned*)&zo;
        } else {
            ((float2*)out)[(size_t)gw * 32 + lane] = z;
        }
    }
}

// ---------------- launch ----------------
extern "C" void kernel_launch(void* const* d_in, const int* in_sizes, int n_in,
                              void* d_out, int out_size) {
    const float* x    = (const float*)d_in[0];
    const void*  edge = d_in[1];
    const float* W1  = (const float*)d_in[2];
    const float* b1  = (const float*)d_in[3];
    const float* W2  = (const float*)d_in[4];
    const float* b2  = (const float*)d_in[5];
    const float* aw1 = (const float*)d_in[6];
    const float* ab1 = (const float*)d_in[7];
    const float* aw2 = (const float*)d_in[8];
    const float* ab2 = (const float*)d_in[9];
    float* out = (float*)d_out;

    float *dinv;
    __half *h1, *y1, *h2;
    int *cnt, *row_ptr, *fill, *col_idx, *blocksum;
    cudaGetSymbolAddress((void**)&dinv,     g_dinv);
    cudaGetSymbolAddress((void**)&h1,       g_h1);
    cudaGetSymbolAddress((void**)&y1,       g_y1);
    cudaGetSymbolAddress((void**)&h2,       g_h2);
    cudaGetSymbolAddress((void**)&cnt,      g_cnt);
    cudaGetSymbolAddress((void**)&row_ptr,  g_row_ptr);
    cudaGetSymbolAddress((void**)&fill,     g_fill);
    cudaGetSymbolAddress((void**)&col_idx,  g_col_idx);
    cudaGetSymbolAddress((void**)&blocksum, g_blocksum);

    static cudaStream_t s1 = nullptr;
    static cudaEvent_t evA = nullptr, evB = nullptr;
    if (s1 == nullptr) {
        cudaStreamCreateWithFlags(&s1, cudaStreamNonBlocking);
        cudaEventCreateWithFlags(&evA, cudaEventDisableTiming);
        cudaEventCreateWithFlags(&evB, cudaEventDisableTiming);
    }

    const int T = 256;

    // fork: full CSR chain on s1, GEMM1 on main stream
    cudaEventRecord(evA, 0);
    cudaStreamWaitEvent(s1, evA, 0);

    detect_edge_dtype_kernel<<<1, 32, 0, s1>>>(edge);
    zero_cnt_kernel<<<(N_NODES + T - 1) / T, T, 0, s1>>>(cnt);
    convert_edges_kernel<<<(2 * N_EDGES + T - 1) / T, T, 0, s1>>>(edge, cnt);
    scan_block_kernel<<<SCAN_BLOCKS, 1024, 0, s1>>>(cnt, row_ptr, dinv, blocksum);
    scan_tops_kernel<<<1, 64, 0, s1>>>(blocksum, row_ptr);
    scan_add_kernel<<<SCAN_BLOCKS, 1024, 0, s1>>>(row_ptr, blocksum, fill);
    fill_csr_kernel<<<(N_EDGES + T - 1) / T, T, 0, s1>>>(fill, col_idx);
    cudaEventRecord(evB, s1);

    // GEMM1 (fp32 inputs converted to fp16 in load stage)
    {
        dim3 grid(DIM_HID / BN, (N_NODES + BM - 1) / BM);
        gemm_half_kernel<false><<<grid, 256>>>(x, W1, h1, N_NODES, DIM_IN, DIM_HID);
    }

    // join
    cudaStreamWaitEvent(0, evB, 0);

    gather_gate_kernel<DIM_HID, true, true><<<(N_NODES * 32 + T - 1) / T, T>>>(
        h1, row_ptr, col_idx, dinv, b1, aw1, ab1, y1);

    // GEMM2 (fp16 A direct)
    {
        dim3 grid(DIM_OUT / BN, (N_NODES + BM - 1) / BM);
        gemm_half_kernel<true><<<grid, 256>>>(y1, W2, h2, N_NODES, DIM_HID, DIM_OUT);
    }

    gather_gate_kernel<DIM_OUT, false, false><<<(N_NODES * 32 + T - 1) / T, T>>>(
        h2, row_ptr, col_idx, dinv, b2, aw2, ab2, out);
}

// round 10
// speedup vs baseline: 3.8291x; 1.0376x over previous
#include <cuda_runtime.h>
#include <cuda_fp16.h>
#include <math.h>

#define N_NODES 50000
#define N_EDGES 800000
#define DIM_IN  256
#define DIM_HID 128
#define DIM_OUT 64
#define SCAN_BLOCKS ((N_NODES + 1023) / 1024)   // 49

// ---------------- device scratch (no allocation allowed) ----------------
__device__ float  g_dinv[N_NODES];
__device__ __half g_h1[N_NODES * DIM_HID];   // GEMM1 out (fp16)
__device__ __half g_y1[N_NODES * DIM_HID];   // gather1 out (fp16, GEMM2 in)
__device__ __half g_h2[N_NODES * DIM_OUT];   // GEMM2 out (fp16)
__device__ int   g_src[N_EDGES];
__device__ int   g_dst[N_EDGES];
__device__ int   g_cnt[N_NODES];
__device__ int   g_row_ptr[N_NODES + 1];
__device__ int   g_fill[N_NODES];
__device__ int2  g_col[N_EDGES];             // packed {src, __float_as_int(dinv[src])}
__device__ unsigned long long g_scanstate[SCAN_BLOCKS];

// ---------------- convert edges (inline dtype detect) + count in-degree ----------------
__global__ void convert_edges_kernel(const void* edge, int* cnt) {
    __shared__ int s_is64;
    if (threadIdx.x == 0) {
        const long long* e64 = (const long long*)edge;
        int ok = 1;
        #pragma unroll
        for (int i = 0; i < 16; i++) {
            long long v = e64[i];
            if (v < 0 || v >= (long long)N_NODES) { ok = 0; break; }
        }
        s_is64 = ok;
    }
    __syncthreads();
    int i = blockIdx.x * blockDim.x + threadIdx.x;
    if (i >= 2 * N_EDGES) return;
    int v;
    if (s_is64) v = (int)((const long long*)edge)[i];
    else        v = ((const int*)edge)[i];
    if (i < N_EDGES) g_src[i] = v;
    else {
        g_dst[i - N_EDGES] = v;
        atomicAdd(&cnt[v], 1);
    }
}

// ---------------- single-kernel decoupled-lookback scan ----------------
// row_ptr = exclusive_scan(cnt); fill = row_ptr; dinv = rsqrt(cnt+1); row_ptr[N] = E
__global__ __launch_bounds__(1024)
void scan_lookback_kernel(const int* __restrict__ cnt,
                          int* __restrict__ row_ptr,
                          float* __restrict__ dinv,
                          int* __restrict__ fill,
                          unsigned long long* __restrict__ state) {
    __shared__ int ws[32];
    __shared__ int s_prefix;
    const int t = threadIdx.x;
    const int lane = t & 31, w = t >> 5;
    const int b = blockIdx.x;
    const int i = b * 1024 + t;

    int val = (i < N_NODES) ? cnt[i] : 0;

    // block-local inclusive scan
    int v = val;
    #pragma unroll
    for (int off = 1; off < 32; off <<= 1) {
        int u = __shfl_up_sync(0xffffffffu, v, off);
        if (lane >= off) v += u;
    }
    if (lane == 31) ws[w] = v;
    __syncthreads();
    if (w == 0) {
        int x = ws[lane];
        #pragma unroll
        for (int off = 1; off < 32; off <<= 1) {
            int u = __shfl_up_sync(0xffffffffu, x, off);
            if (lane >= off) x += u;
        }
        ws[lane] = x;
    }
    __syncthreads();
    int incl  = v + (w > 0 ? ws[w - 1] : 0);
    int total = ws[31];   // block total

    // publish aggregate (status 1 in bit 32)
    if (t == 0)
        atomicExch(&state[b], (1ULL << 32) | (unsigned long long)(unsigned)total);

    // parallel lookback: thread t polls predecessor t (t < b)
    int partial = 0;
    if (t < b) {
        unsigned long long s;
        do {
            s = *(volatile unsigned long long*)&state[t];
        } while ((s >> 32) == 0ULL);
        partial = (int)(unsigned)s;
    }
    __syncthreads();   // ws reuse barrier
    // block reduce partials
    #pragma unroll
    for (int off = 16; off > 0; off >>= 1)
        partial += __shfl_xor_sync(0xffffffffu, partial, off);
    if (lane == 0) ws[w] = partial;
    __syncthreads();
    if (w == 0) {
        int x = ws[lane];
        #pragma unroll
        for (int off = 16; off > 0; off >>= 1)
            x += __shfl_xor_sync(0xffffffffu, x, off);
        if (lane == 0) s_prefix = x;
    }
    __syncthreads();
    int prefix = s_prefix;

    if (i < N_NODES) {
        int excl = prefix + incl - val;
        row_ptr[i] = excl;
        fill[i]    = excl;
        dinv[i]    = rsqrtf((float)val + 1.0f);
    }
    if (b == SCAN_BLOCKS - 1 && t == 0)
        row_ptr[N_NODES] = prefix + total;
}

// ---------------- fill CSR with packed (src, dinv[src]) ----------------
__global__ void fill_csr_kernel(int* __restrict__ fill,
                                int2* __restrict__ col,
                                const float* __restrict__ dinv) {
    int e = blockIdx.x * blockDim.x + threadIdx.x;
    if (e >= N_EDGES) return;
    int d = g_dst[e];
    int s = g_src[e];
    int pos = atomicAdd(&fill[d], 1);
    col[pos] = make_int2(s, __float_as_int(dinv[s]));
}

// ---------------- unified fp16 tensor-core GEMM ----------------
// H(fp16)[M,N] = A[M,K] @ B(fp32)[K,N]
// Block 128x64, BK=64, 8 warps 4(M)x2(N), warp tile 32x32 = 2x4 m16n8k16.
#define BM 128
#define BN 64
#define BKH 64
#define ASH_STRIDE 72
#define BSH_STRIDE 72

template<bool A_FP16>
__global__ __launch_bounds__(256)
void gemm_half_kernel(const void* __restrict__ Av,
                      const float* __restrict__ B,
                      __half* __restrict__ H,
                      int M, int K, int N) {
    __shared__ __half As[BM * ASH_STRIDE];
    __shared__ __half Bs[BN * BSH_STRIDE];

    const int tid  = threadIdx.x;
    const int warp = tid >> 5;
    const int lane = tid & 31;
    const int wr = (warp & 3) * 32;
    const int wc = (warp >> 2) * 32;
    const int block_row = blockIdx.y * BM;
    const int block_col = blockIdx.x * BN;

    const int lq = lane >> 2;
    const int lr = lane & 3;

    float acc[2][4][4];
    #pragma unroll
    for (int mt = 0; mt < 2; mt++)
        #pragma unroll
        for (int nt = 0; nt < 4; nt++)
            #pragma unroll
            for (int i = 0; i < 4; i++) acc[mt][nt][i] = 0.0f;

    float4 rA32[8];
    uint4  rA16[4];
    float  rB[16];

    auto load_tile = [&](int k0) {
        if constexpr (!A_FP16) {
            const float* A = (const float*)Av;
            #pragma unroll
            for (int l = 0; l < 8; l++) {
                int idx = tid + l * 256;
                int r  = idx >> 4;
                int c4 = idx & 15;
                int gr = block_row + r;
                rA32[l] = make_float4(0.f, 0.f, 0.f, 0.f);
                if (gr < M)
                    rA32[l] = *(const float4*)&A[(size_t)gr * K + k0 + c4 * 4];
            }
        } else {
            const __half* A = (const __half*)Av;
            #pragma unroll
            for (int l = 0; l < 4; l++) {
                int idx = tid + l * 256;
                int r  = idx >> 3;
                int c8 = idx & 7;
                int gr = block_row + r;
                rA16[l] = make_uint4(0u, 0u, 0u, 0u);
                if (gr < M)
                    rA16[l] = *(const uint4*)&A[(size_t)gr * K + k0 + c8 * 8];
            }
        }
        #pragma unroll
        for (int l = 0; l < 16; l++) {
            int idx = tid + l * 256;
            int k = idx >> 6;
            int n = idx & 63;
            rB[l] = B[(size_t)(k0 + k) * N + block_col + n];
        }
    };

    auto store_tile = [&]() {
        if constexpr (!A_FP16) {
            #pragma unroll
            for (int l = 0; l < 8; l++) {
                int idx = tid + l * 256;
                int r  = idx >> 4;
                int c4 = idx & 15;
                __half2 h01 = __floats2half2_rn(rA32[l].x, rA32[l].y);
                __half2 h23 = __floats2half2_rn(rA32[l].z, rA32[l].w);
                uint2 u;
                u.x = *(unsigned*)&h01; u.y = *(unsigned*)&h23;
                *(uint2*)&As[r * ASH_STRIDE + c4 * 4] = u;
            }
        } else {
            #pragma unroll
            for (int l = 0; l < 4; l++) {
                int idx = tid + l * 256;
                int r  = idx >> 3;
                int c8 = idx & 7;
                *(uint4*)&As[r * ASH_STRIDE + c8 * 8] = rA16[l];
            }
        }
        #pragma unroll
        for (int l = 0; l < 16; l++) {
            int idx = tid + l * 256;
            int k = idx >> 6;
            int n = idx & 63;
            Bs[n * BSH_STRIDE + k] = __float2half_rn(rB[l]);
        }
    };

    auto compute = [&]() {
        #pragma unroll
        for (int kk = 0; kk < BKH; kk += 16) {
            unsigned a[2][4], b[4][2];
            #pragma unroll
            for (int mt = 0; mt < 2; mt++) {
                int r1 = wr + mt * 16 + lq;
                a[mt][0] = *(const unsigned*)&As[r1 * ASH_STRIDE + kk + lr * 2];
                a[mt][1] = *(const unsigned*)&As[(r1 + 8) * ASH_STRIDE + kk + lr * 2];
                a[mt][2] = *(const unsigned*)&As[r1 * ASH_STRIDE + kk + lr * 2 + 8];
                a[mt][3] = *(const unsigned*)&As[(r1 + 8) * ASH_STRIDE + kk + lr * 2 + 8];
            }
            #pragma unroll
            for (int nt = 0; nt < 4; nt++) {
                int c = wc + nt * 8 + lq;
                b[nt][0] = *(const unsigned*)&Bs[c * BSH_STRIDE + kk + lr * 2];
                b[nt][1] = *(const unsigned*)&Bs[c * BSH_STRIDE + kk + lr * 2 + 8];
            }
            #pragma unroll
            for (int mt = 0; mt < 2; mt++)
                #pragma unroll
                for (int nt = 0; nt < 4; nt++) {
                    asm volatile(
                        "mma.sync.aligned.m16n8k16.row.col.f32.f16.f16.f32 "
                        "{%0,%1,%2,%3}, {%4,%5,%6,%7}, {%8,%9}, {%0,%1,%2,%3};"
                        : "+f"(acc[mt][nt][0]), "+f"(acc[mt][nt][1]),
                          "+f"(acc[mt][nt][2]), "+f"(acc[mt][nt][3])
                        : "r"(a[mt][0]), "r"(a[mt][1]), "r"(a[mt][2]), "r"(a[mt][3]),
                          "r"(b[nt][0]), "r"(b[nt][1]));
                }
        }
    };

    load_tile(0);
    store_tile();
    __syncthreads();

    for (int k0 = BKH; k0 < K; k0 += BKH) {
        load_tile(k0);
        compute();
        __syncthreads();
        store_tile();
        __syncthreads();
    }
    compute();

    #pragma unroll
    for (int mt = 0; mt < 2; mt++) {
        int r0 = block_row + wr + mt * 16 + lq;
        int r1 = r0 + 8;
        #pragma unroll
        for (int nt = 0; nt < 4; nt++) {
            int c = block_col + wc + nt * 8 + lr * 2;
            if (r0 < M)
                *(__half2*)&H[(size_t)r0 * N + c] = __floats2half2_rn(acc[mt][nt][0], acc[mt][nt][1]);
            if (r1 < M)
                *(__half2*)&H[(size_t)r1 * N + c] = __floats2half2_rn(acc[mt][nt][2], acc[mt][nt][3]);
        }
    }
}

// ---------------- fused CSR gather (packed entries) + bias + (relu) + gate ----------------
template<int C, bool RELU, bool OUT_HALF>
__global__ void gather_gate_kernel(const __half* __restrict__ h,
                                   const int* __restrict__ row_ptr,
                                   const int2* __restrict__ col,
                                   const float* __restrict__ dinv,
                                   const float* __restrict__ bias,
                                   const float* __restrict__ aw,
                                   const float* __restrict__ ab,
                                   void* __restrict__ out) {
    int gw   = (blockIdx.x * blockDim.x + threadIdx.x) >> 5;
    int lane = threadIdx.x & 31;
    if (gw >= N_NODES) return;

    float di = dinv[gw];

    if constexpr (C == 128) {
        const uint2* base = (const uint2*)h;
        uint2 u = base[(size_t)gw * 32 + lane];
        float2 p0 = __half22float2(*(__half2*)&u.x);
        float2 p1 = __half22float2(*(__half2*)&u.y);
        float4 acc = make_float4(p0.x * di, p0.y * di, p1.x * di, p1.y * di);

        int p = row_ptr[gw], pe = row_ptr[gw + 1];
        for (; p + 8 <= pe; p += 8) {
            int2 e[8]; uint2 ui[8];
            #pragma unroll
            for (int q = 0; q < 8; q++) e[q] = col[p + q];
            #pragma unroll
            for (int q = 0; q < 8; q++) ui[q] = base[(size_t)e[q].x * 32 + lane];
            #pragma unroll
            for (int q = 0; q < 8; q++) {
                float w = __int_as_float(e[q].y);
                float2 a = __half22float2(*(__half2*)&ui[q].x);
                float2 b = __half22float2(*(__half2*)&ui[q].y);
                acc.x += a.x * w; acc.y += a.y * w;
                acc.z += b.x * w; acc.w += b.y * w;
            }
        }
        for (; p < pe; p++) {
            int2 ec = col[p];
            float w = __int_as_float(ec.y);
            uint2 us = base[(size_t)ec.x * 32 + lane];
            float2 a = __half22float2(*(__half2*)&us.x);
            float2 b = __half22float2(*(__half2*)&us.y);
            acc.x += a.x*w; acc.y += a.y*w; acc.z += b.x*w; acc.w += b.y*w;
        }
        float4 b = ((const float4*)bias)[lane];
        float4 z;
        z.x = acc.x * di + b.x; z.y = acc.y * di + b.y;
        z.z = acc.z * di + b.z; z.w = acc.w * di + b.w;
        if (RELU) {
            z.x = fmaxf(z.x, 0.f); z.y = fmaxf(z.y, 0.f);
            z.z = fmaxf(z.z, 0.f); z.w = fmaxf(z.w, 0.f);
        }
        float4 a = ((const float4*)aw)[lane];
        float dot = z.x * a.x + z.y * a.y + z.z * a.z + z.w * a.w;
        #pragma unroll
        for (int off = 16; off > 0; off >>= 1)
            dot += __shfl_xor_sync(0xffffffffu, dot, off);
        float g = 1.0f / (1.0f + expf(-(dot + ab[0])));
        z.x *= g; z.y *= g; z.z *= g; z.w *= g;
        if constexpr (OUT_HALF) {
            __half2 z01 = __floats2half2_rn(z.x, z.y);
            __half2 z23 = __floats2half2_rn(z.z, z.w);
            uint2 uo;
            uo.x = *(unsigned*)&z01; uo.y = *(unsigned*)&z23;
            ((uint2*)out)[(size_t)gw * 32 + lane] = uo;
        } else {
            ((float4*)out)[(size_t)gw * 32 + lane] = z;
        }
    } else {
        const unsigned* base = (const unsigned*)h;
        unsigned u = base[(size_t)gw * 32 + lane];
        float2 ps = __half22float2(*(__half2*)&u);
        float2 acc = make_float2(ps.x * di, ps.y * di);

        int p = row_ptr[gw], pe = row_ptr[gw + 1];
        for (; p + 8 <= pe; p += 8) {
            int2 e[8]; unsigned ui[8];
            #pragma unroll
            for (int q = 0; q < 8; q++) e[q] = col[p + q];
            #pragma unroll
            for (int q = 0; q < 8; q++) ui[q] = base[(size_t)e[q].x * 32 + lane];
            #pragma unroll
            for (int q = 0; q < 8; q++) {
                float w = __int_as_float(e[q].y);
                float2 v = __half22float2(*(__half2*)&ui[q]);
                acc.x += v.x * w; acc.y += v.y * w;
            }
        }
        for (; p < pe; p++) {
            int2 ec = col[p];
            float w = __int_as_float(ec.y);
            unsigned us = base[(size_t)ec.x * 32 + lane];
            float2 v = __half22float2(*(__half2*)&us);
            acc.x += v.x*w; acc.y += v.y*w;
        }
        float2 b = ((const float2*)bias)[lane];
        float2 z;
        z.x = acc.x * di + b.x; z.y = acc.y * di + b.y;
        if (RELU) { z.x = fmaxf(z.x, 0.f); z.y = fmaxf(z.y, 0.f); }
        float2 a = ((const float2*)aw)[lane];
        float dot = z.x * a.x + z.y * a.y;
        #pragma unroll
        for (int off = 16; off > 0; off >>= 1)
            dot += __shfl_xor_sync(0xffffffffu, dot, off);
        float g = 1.0f / (1.0f + expf(-(dot + ab[0])));
        z.x *= g; z.y *= g;
        if constexpr (OUT_HALF) {
            __half2 zo = __floats2half2_rn(z.x, z.y);
            ((unsigned*)out)[(size_t)gw * 32 + lane] = *(unsigned*)&zo;
        } else {
            ((float2*)out)[(size_t)gw * 32 + lane] = z;
        }
    }
}

// ---------------- launch ----------------
extern "C" void kernel_launch(void* const* d_in, const int* in_sizes, int n_in,
                              void* d_out, int out_size) {
    const float* x    = (const float*)d_in[0];
    const void*  edge = d_in[1];
    const float* W1  = (const float*)d_in[2];
    const float* b1  = (const float*)d_in[3];
    const float* W2  = (const float*)d_in[4];
    const float* b2  = (const float*)d_in[5];
    const float* aw1 = (const float*)d_in[6];
    const float* ab1 = (const float*)d_in[7];
    const float* aw2 = (const float*)d_in[8];
    const float* ab2 = (const float*)d_in[9];
    float* out = (float*)d_out;

    float *dinv;
    __half *h1, *y1, *h2;
    int *cnt, *row_ptr, *fill;
    int2 *col;
    unsigned long long *state;
    cudaGetSymbolAddress((void**)&dinv,    g_dinv);
    cudaGetSymbolAddress((void**)&h1,      g_h1);
    cudaGetSymbolAddress((void**)&y1,      g_y1);
    cudaGetSymbolAddress((void**)&h2,      g_h2);
    cudaGetSymbolAddress((void**)&cnt,     g_cnt);
    cudaGetSymbolAddress((void**)&row_ptr, g_row_ptr);
    cudaGetSymbolAddress((void**)&fill,    g_fill);
    cudaGetSymbolAddress((void**)&col,     g_col);
    cudaGetSymbolAddress((void**)&state,   g_scanstate);

    static cudaStream_t s1 = nullptr;
    static cudaEvent_t evA = nullptr, evB = nullptr;
    if (s1 == nullptr) {
        cudaStreamCreateWithFlags(&s1, cudaStreamNonBlocking);
        cudaEventCreateWithFlags(&evA, cudaEventDisableTiming);
        cudaEventCreateWithFlags(&evB, cudaEventDisableTiming);
    }

    const int T = 256;

    // fork: CSR chain on s1, GEMM1 on main stream
    cudaEventRecord(evA, 0);
    cudaStreamWaitEvent(s1, evA, 0);

    cudaMemsetAsync(cnt,   0, N_NODES * sizeof(int), s1);
    cudaMemsetAsync(state, 0, SCAN_BLOCKS * sizeof(unsigned long long), s1);
    convert_edges_kernel<<<(2 * N_EDGES + T - 1) / T, T, 0, s1>>>(edge, cnt);
    scan_lookback_kernel<<<SCAN_BLOCKS, 1024, 0, s1>>>(cnt, row_ptr, dinv, fill, state);
    fill_csr_kernel<<<(N_EDGES + T - 1) / T, T, 0, s1>>>(fill, col, dinv);
    cudaEventRecord(evB, s1);

    // GEMM1 (fp32 inputs converted to fp16 in load stage)
    {
        dim3 grid(DIM_HID / BN, (N_NODES + BM - 1) / BM);
        gemm_half_kernel<false><<<grid, 256>>>(x, W1, h1, N_NODES, DIM_IN, DIM_HID);
    }

    // join
    cudaStreamWaitEvent(0, evB, 0);

    gather_gate_kernel<DIM_HID, true, true><<<(N_NODES * 32 + T - 1) / T, T>>>(
        h1, row_ptr, col, dinv, b1, aw1, ab1, y1);

    // GEMM2 (fp16 A direct)
    {
        dim3 grid(DIM_OUT / BN, (N_NODES + BM - 1) / BM);
        gemm_half_kernel<true><<<grid, 256>>>(y1, W2, h2, N_NODES, DIM_HID, DIM_OUT);
    }

    gather_gate_kernel<DIM_OUT, false, false><<<(N_NODES * 32 + T - 1) / T, T>>>(
        h2, row_ptr, col, dinv, b2, aw2, ab2, out);
}

// round 13
// speedup vs baseline: 4.2072x; 1.0987x over previous
#include <cuda_runtime.h>
#include <cuda_fp16.h>
#include <stdint.h>
#include <math.h>

#define N_NODES 50000
#define N_EDGES 800000
#define DIM_IN  256
#define DIM_HID 128
#define DIM_OUT 64
#define SCAN_BLOCKS ((N_NODES + 1023) / 1024)   // 49

// ---------------- device scratch (no allocation allowed) ----------------
__device__ float  g_dinv[N_NODES];
__device__ __half g_xh[N_NODES * DIM_IN];    // x converted to fp16
__device__ __half g_w1t[DIM_HID * DIM_IN];   // W1^T fp16 [N][K]
__device__ __half g_w2t[DIM_OUT * DIM_HID];  // W2^T fp16 [N][K]
__device__ __half g_h1[N_NODES * DIM_HID];
__device__ __half g_y1[N_NODES * DIM_HID];
__device__ __half g_h2[N_NODES * DIM_OUT];
__device__ int   g_src[N_EDGES];
__device__ int   g_dst[N_EDGES];
__device__ int   g_cnt[N_NODES];
__device__ int   g_row_ptr[N_NODES + 1];
__device__ int   g_fill[N_NODES];
__device__ int2  g_col[N_EDGES];             // packed {src, dinv[src] bits}
__device__ unsigned long long g_scanstate[SCAN_BLOCKS];

// ---------------- converters ----------------
__global__ void convert_x_kernel(const float* __restrict__ x,
                                 __half* __restrict__ xh, int n8) {
    int i = blockIdx.x * blockDim.x + threadIdx.x;
    if (i >= n8) return;
    const float4* src = (const float4*)x;
    float4 v0 = src[2 * i], v1 = src[2 * i + 1];
    uint4 o; __half2 h;
    h = __floats2half2_rn(v0.x, v0.y); o.x = *(unsigned*)&h;
    h = __floats2half2_rn(v0.z, v0.w); o.y = *(unsigned*)&h;
    h = __floats2half2_rn(v1.x, v1.y); o.z = *(unsigned*)&h;
    h = __floats2half2_rn(v1.z, v1.w); o.w = *(unsigned*)&h;
    ((uint4*)xh)[i] = o;
}

// Wt[n][k] = W[k][n]  (one block per n)
__global__ void convert_wt_kernel(const float* __restrict__ W,
                                  __half* __restrict__ Wt, int K, int N) {
    int n = blockIdx.x;
    for (int k = threadIdx.x; k < K; k += blockDim.x)
        Wt[(size_t)n * K + k] = __float2half_rn(W[(size_t)k * N + n]);
}

// ---------------- convert edges (inline dtype detect) + count in-degree ----------------
__global__ void convert_edges_kernel(const void* edge, int* cnt) {
    __shared__ int s_is64;
    if (threadIdx.x == 0) {
        const long long* e64 = (const long long*)edge;
        int ok = 1;
        #pragma unroll
        for (int i = 0; i < 16; i++) {
            long long v = e64[i];
            if (v < 0 || v >= (long long)N_NODES) { ok = 0; break; }
        }
        s_is64 = ok;
    }
    __syncthreads();
    int i = blockIdx.x * blockDim.x + threadIdx.x;
    if (i >= 2 * N_EDGES) return;
    int v;
    if (s_is64) v = (int)((const long long*)edge)[i];
    else        v = ((const int*)edge)[i];
    if (i < N_EDGES) g_src[i] = v;
    else {
        g_dst[i - N_EDGES] = v;
        atomicAdd(&cnt[v], 1);
    }
}

// ---------------- single-kernel decoupled-lookback scan ----------------
__global__ __launch_bounds__(1024)
void scan_lookback_kernel(const int* __restrict__ cnt,
                          int* __restrict__ row_ptr,
                          float* __restrict__ dinv,
                          int* __restrict__ fill,
                          unsigned long long* __restrict__ state) {
    __shared__ int ws[32];
    __shared__ int s_prefix;
    const int t = threadIdx.x;
    const int lane = t & 31, w = t >> 5;
    const int b = blockIdx.x;
    const int i = b * 1024 + t;

    int val = (i < N_NODES) ? cnt[i] : 0;

    int v = val;
    #pragma unroll
    for (int off = 1; off < 32; off <<= 1) {
        int u = __shfl_up_sync(0xffffffffu, v, off);
        if (lane >= off) v += u;
    }
    if (lane == 31) ws[w] = v;
    __syncthreads();
    if (w == 0) {
        int x = ws[lane];
        #pragma unroll
        for (int off = 1; off < 32; off <<= 1) {
            int u = __shfl_up_sync(0xffffffffu, x, off);
            if (lane >= off) x += u;
        }
        ws[lane] = x;
    }
    __syncthreads();
    int incl  = v + (w > 0 ? ws[w - 1] : 0);
    int total = ws[31];

    if (t == 0)
        atomicExch(&state[b], (1ULL << 32) | (unsigned long long)(unsigned)total);

    int partial = 0;
    if (t < b) {
        unsigned long long s;
        do {
            s = *(volatile unsigned long long*)&state[t];
        } while ((s >> 32) == 0ULL);
        partial = (int)(unsigned)s;
    }
    __syncthreads();
    #pragma unroll
    for (int off = 16; off > 0; off >>= 1)
        partial += __shfl_xor_sync(0xffffffffu, partial, off);
    if (lane == 0) ws[w] = partial;
    __syncthreads();
    if (w == 0) {
        int x = ws[lane];
        #pragma unroll
        for (int off = 16; off > 0; off >>= 1)
            x += __shfl_xor_sync(0xffffffffu, x, off);
        if (lane == 0) s_prefix = x;
    }
    __syncthreads();
    int prefix = s_prefix;

    if (i < N_NODES) {
        int excl = prefix + incl - val;
        row_ptr[i] = excl;
        fill[i]    = excl;
        dinv[i]    = rsqrtf((float)val + 1.0f);
    }
    if (b == SCAN_BLOCKS - 1 && t == 0)
        row_ptr[N_NODES] = prefix + total;
}

__global__ void fill_csr_kernel(int* __restrict__ fill,
                                int2* __restrict__ col,
                                const float* __restrict__ dinv) {
    int e = blockIdx.x * blockDim.x + threadIdx.x;
    if (e >= N_EDGES) return;
    int d = g_dst[e];
    int s = g_src[e];
    int pos = atomicAdd(&fill[d], 1);
    col[pos] = make_int2(s, __float_as_int(dinv[s]));
}

// ---------------- fp16 pipelined GEMM: H[M,N] = A[M,K] @ Bt[N,K]^T ----------------
// Block 128x64, BK=64, 256 threads (8 warps, 4Mx2N), warp tile 32x32.
// cp.async 2-stage double buffer, XOR-swizzled smem, ldmatrix fragments.
#define BMH 128
#define BNH 64
#define BKH 64
#define A_TILE_B (BMH * BKH * 2)            // 16384 bytes
#define B_TILE_B (BNH * BKH * 2)            // 8192 bytes
#define STAGE_B  (A_TILE_B + B_TILE_B)      // 24576 bytes

// rows are 64 halves = 128B = 8x16B chunks; chunk index ^= (row & 7)
__device__ __forceinline__ uint32_t swz(uint32_t row, uint32_t halfcol) {
    return row * 128u + ((((halfcol >> 3) ^ (row & 7)) << 4) | ((halfcol & 7) << 1));
}

__device__ __forceinline__ void gemm_issue(
    uint32_t abase, uint32_t bbase,
    const __half* __restrict__ A, const __half* __restrict__ Bt,
    int block_row, int block_col, int M, int K, int k0,
    int ld_row, int ld_chunk)
{
    #pragma unroll
    for (int l = 0; l < 4; l++) {
        int r  = ld_row + l * 32;
        int gr = block_row + r;
        int sz = (gr < M) ? 16 : 0;
        int grc = (gr < M) ? gr : (M - 1);
        const __half* srcp = A + (size_t)grc * K + k0 + ld_chunk * 8;
        uint32_t dsta = abase + swz((uint32_t)r, (uint32_t)(ld_chunk * 8));
        asm volatile("cp.async.cg.shared.global [%0], [%1], 16, %2;"
                     :: "r"(dsta), "l"(srcp), "r"(sz));
    }
    #pragma unroll
    for (int l = 0; l < 2; l++) {
        int n = ld_row + l * 32;
        const __half* srcp = Bt + (size_t)(block_col + n) * K + k0 + ld_chunk * 8;
        uint32_t dstb = bbase + swz((uint32_t)n, (uint32_t)(ld_chunk * 8));
        asm volatile("cp.async.cg.shared.global [%0], [%1], 16, 16;"
                     :: "r"(dstb), "l"(srcp));
    }
}

__device__ __forceinline__ void gemm_compute(
    uint32_t abase, uint32_t bbase,
    int wr, int wc, int lane,
    float (&acc)[2][4][4])
{
    #pragma unroll
    for (int kk = 0; kk < BKH; kk += 16) {
        uint32_t fa[2][4];
        uint32_t fb[2][4];
        #pragma unroll
        for (int mt = 0; mt < 2; mt++) {
            uint32_t arow = (uint32_t)(wr + mt * 16 + (lane & 15));
            uint32_t acol = (uint32_t)(kk + ((lane >> 4) << 3));
            uint32_t aaddr = abase + swz(arow, acol);
            asm volatile("ldmatrix.sync.aligned.m8n8.x4.shared.b16 {%0,%1,%2,%3}, [%4];"
                : "=r"(fa[mt][0]), "=r"(fa[mt][1]), "=r"(fa[mt][2]), "=r"(fa[mt][3])
                : "r"(aaddr));
        }
        #pragma unroll
        for (int np = 0; np < 2; np++) {
            uint32_t grp  = (uint32_t)(lane >> 3);
            uint32_t brow = (uint32_t)(wc + np * 16 + (lane & 7)) + ((grp >> 1) << 3);
            uint32_t bcol = (uint32_t)kk + ((grp & 1) << 3);
            uint32_t baddr = bbase + swz(brow, bcol);
            asm volatile("ldmatrix.sync.aligned.m8n8.x4.shared.b16 {%0,%1,%2,%3}, [%4];"
                : "=r"(fb[np][0]), "=r"(fb[np][1]), "=r"(fb[np][2]), "=r"(fb[np][3])
                : "r"(baddr));
        }
        #pragma unroll
        for (int mt = 0; mt < 2; mt++) {
            #pragma unroll
            for (int nt = 0; nt < 4; nt++) {
                uint32_t bb0 = fb[nt >> 1][(nt & 1) * 2];
                uint32_t bb1 = fb[nt >> 1][(nt & 1) * 2 + 1];
                asm volatile(
                    "mma.sync.aligned.m16n8k16.row.col.f32.f16.f16.f32 "
                    "{%0,%1,%2,%3}, {%4,%5,%6,%7}, {%8,%9}, {%0,%1,%2,%3};"
                    : "+f"(acc[mt][nt][0]), "+f"(acc[mt][nt][1]),
                      "+f"(acc[mt][nt][2]), "+f"(acc[mt][nt][3])
                    : "r"(fa[mt][0]), "r"(fa[mt][1]), "r"(fa[mt][2]), "r"(fa[mt][3]),
                      "r"(bb0), "r"(bb1));
            }
        }
    }
}

__global__ __launch_bounds__(256)
void gemm_fp16_pipe(const __half* __restrict__ A,
                    const __half* __restrict__ Bt,
                    __half* __restrict__ H,
                    int M, int K, int N) {
    __shared__ char smem[2 * STAGE_B];      // 48 KB
    uint32_t sbase = (uint32_t)__cvta_generic_to_shared(smem);

    const int tid  = threadIdx.x;
    const int warp = tid >> 5;
    const int lane = tid & 31;
    const int wr = (warp & 3) * 32;
    const int wc = (warp >> 2) * 32;
    const int block_row = blockIdx.y * BMH;
    const int block_col = blockIdx.x * BNH;
    const int lq = lane >> 2;
    const int lr = lane & 3;

    float acc[2][4][4];
    #pragma unroll
    for (int mt = 0; mt < 2; mt++)
        #pragma unroll
        for (int nt = 0; nt < 4; nt++)
            #pragma unroll
            for (int i = 0; i < 4; i++) acc[mt][nt][i] = 0.0f;

    const int ld_row   = tid >> 3;   // 0..31
    const int ld_chunk = tid & 7;    // 0..7 (16B chunks)

    const int NIT = K / BKH;
    gemm_issue(sbase, sbase + A_TILE_B, A, Bt, block_row, block_col, M, K, 0, ld_row, ld_chunk);
    asm volatile("cp.async.commit_group;");

    for (int it = 0; it < NIT; it++) {
        if (it + 1 < NIT) {
            uint32_t nb = sbase + ((it + 1) & 1) * STAGE_B;
            gemm_issue(nb, nb + A_TILE_B, A, Bt, block_row, block_col, M, K,
                       (it + 1) * BKH, ld_row, ld_chunk);
            asm volatile("cp.async.commit_group;");
            asm volatile("cp.async.wait_group 1;");
        } else {
            asm volatile("cp.async.wait_group 0;");
        }
        __syncthreads();
        uint32_t cb = sbase + (it & 1) * STAGE_B;
        gemm_compute(cb, cb + A_TILE_B, wr, wc, lane, acc);
        __syncthreads();
    }

    #pragma unroll
    for (int mt = 0; mt < 2; mt++) {
        int r0 = block_row + wr + mt * 16 + lq;
        int r1 = r0 + 8;
        #pragma unroll
        for (int nt = 0; nt < 4; nt++) {
            int c = block_col + wc + nt * 8 + lr * 2;
            if (r0 < M)
                *(__half2*)&H[(size_t)r0 * N + c] = __floats2half2_rn(acc[mt][nt][0], acc[mt][nt][1]);
            if (r1 < M)
                *(__half2*)&H[(size_t)r1 * N + c] = __floats2half2_rn(acc[mt][nt][2], acc[mt][nt][3]);
        }
    }
}

// ---------------- fused CSR gather (packed entries) + bias + (relu) + gate ----------------
template<int C, bool RELU, bool OUT_HALF>
__global__ void gather_gate_kernel(const __half* __restrict__ h,
                                   const int* __restrict__ row_ptr,
                                   const int2* __restrict__ col,
                                   const float* __restrict__ dinv,
                                   const float* __restrict__ bias,
                                   const float* __restrict__ aw,
                                   const float* __restrict__ ab,
                                   void* __restrict__ out) {
    int gw   = (blockIdx.x * blockDim.x + threadIdx.x) >> 5;
    int lane = threadIdx.x & 31;
    if (gw >= N_NODES) return;

    float di = dinv[gw];

    if constexpr (C == 128) {
        const uint2* base = (const uint2*)h;
        uint2 u = base[(size_t)gw * 32 + lane];
        float2 p0 = __half22float2(*(__half2*)&u.x);
        float2 p1 = __half22float2(*(__half2*)&u.y);
        float4 acc = make_float4(p0.x * di, p0.y * di, p1.x * di, p1.y * di);

        int p = row_ptr[gw], pe = row_ptr[gw + 1];
        for (; p + 8 <= pe; p += 8) {
            int2 e[8]; uint2 ui[8];
            #pragma unroll
            for (int q = 0; q < 8; q++) e[q] = col[p + q];
            #pragma unroll
            for (int q = 0; q < 8; q++) ui[q] = base[(size_t)e[q].x * 32 + lane];
            #pragma unroll
            for (int q = 0; q < 8; q++) {
                float w = __int_as_float(e[q].y);
                float2 a = __half22float2(*(__half2*)&ui[q].x);
                float2 b = __half22float2(*(__half2*)&ui[q].y);
                acc.x += a.x * w; acc.y += a.y * w;
                acc.z += b.x * w; acc.w += b.y * w;
            }
        }
        for (; p < pe; p++) {
            int2 ec = col[p];
            float w = __int_as_float(ec.y);
            uint2 us = base[(size_t)ec.x * 32 + lane];
            float2 a = __half22float2(*(__half2*)&us.x);
            float2 b = __half22float2(*(__half2*)&us.y);
            acc.x += a.x*w; acc.y += a.y*w; acc.z += b.x*w; acc.w += b.y*w;
        }
        float4 b = ((const float4*)bias)[lane];
        float4 z;
        z.x = acc.x * di + b.x; z.y = acc.y * di + b.y;
        z.z = acc.z * di + b.z; z.w = acc.w * di + b.w;
        if (RELU) {
            z.x = fmaxf(z.x, 0.f); z.y = fmaxf(z.y, 0.f);
            z.z = fmaxf(z.z, 0.f); z.w = fmaxf(z.w, 0.f);
        }
        float4 a = ((const float4*)aw)[lane];
        float dot = z.x * a.x + z.y * a.y + z.z * a.z + z.w * a.w;
        #pragma unroll
        for (int off = 16; off > 0; off >>= 1)
            dot += __shfl_xor_sync(0xffffffffu, dot, off);
        float g = 1.0f / (1.0f + expf(-(dot + ab[0])));
        z.x *= g; z.y *= g; z.z *= g; z.w *= g;
        if constexpr (OUT_HALF) {
            __half2 z01 = __floats2half2_rn(z.x, z.y);
            __half2 z23 = __floats2half2_rn(z.z, z.w);
            uint2 uo;
            uo.x = *(unsigned*)&z01; uo.y = *(unsigned*)&z23;
            ((uint2*)out)[(size_t)gw * 32 + lane] = uo;
        } else {
            ((float4*)out)[(size_t)gw * 32 + lane] = z;
        }
    } else {
        const unsigned* base = (const unsigned*)h;
        unsigned u = base[(size_t)gw * 32 + lane];
        float2 ps = __half22float2(*(__half2*)&u);
        float2 acc = make_float2(ps.x * di, ps.y * di);

        int p = row_ptr[gw], pe = row_ptr[gw + 1];
        for (; p + 8 <= pe; p += 8) {
            int2 e[8]; unsigned ui[8];
            #pragma unroll
            for (int q = 0; q < 8; q++) e[q] = col[p + q];
            #pragma unroll
            for (int q = 0; q < 8; q++) ui[q] = base[(size_t)e[q].x * 32 + lane];
            #pragma unroll
            for (int q = 0; q < 8; q++) {
                float w = __int_as_float(e[q].y);
                float2 v = __half22float2(*(__half2*)&ui[q]);
                acc.x += v.x * w; acc.y += v.y * w;
            }
        }
        for (; p < pe; p++) {
            int2 ec = col[p];
            float w = __int_as_float(ec.y);
            unsigned us = base[(size_t)ec.x * 32 + lane];
            float2 v = __half22float2(*(__half2*)&us);
            acc.x += v.x*w; acc.y += v.y*w;
        }
        float2 b = ((const float2*)bias)[lane];
        float2 z;
        z.x = acc.x * di + b.x; z.y = acc.y * di + b.y;
        if (RELU) { z.x = fmaxf(z.x, 0.f); z.y = fmaxf(z.y, 0.f); }
        float2 a = ((const float2*)aw)[lane];
        float dot = z.x * a.x + z.y * a.y;
        #pragma unroll
        for (int off = 16; off > 0; off >>= 1)
            dot += __shfl_xor_sync(0xffffffffu, dot, off);
        float g = 1.0f / (1.0f + expf(-(dot + ab[0])));
        z.x *= g; z.y *= g;
        if constexpr (OUT_HALF) {
            __half2 zo = __floats2half2_rn(z.x, z.y);
            ((unsigned*)out)[(size_t)gw * 32 + lane] = *(unsigned*)&zo;
        } else {
            ((float2*)out)[(size_t)gw * 32 + lane] = z;
        }
    }
}

// ---------------- launch ----------------
extern "C" void kernel_launch(void* const* d_in, const int* in_sizes, int n_in,
                              void* d_out, int out_size) {
    const float* x    = (const float*)d_in[0];
    const void*  edge = d_in[1];
    const float* W1  = (const float*)d_in[2];
    const float* b1  = (const float*)d_in[3];
    const float* W2  = (const float*)d_in[4];
    const float* b2  = (const float*)d_in[5];
    const float* aw1 = (const float*)d_in[6];
    const float* ab1 = (const float*)d_in[7];
    const float* aw2 = (const float*)d_in[8];
    const float* ab2 = (const float*)d_in[9];
    float* out = (float*)d_out;

    float *dinv;
    __half *xh, *w1t, *w2t, *h1, *y1, *h2;
    int *cnt, *row_ptr, *fill;
    int2 *col;
    unsigned long long *state;
    cudaGetSymbolAddress((void**)&dinv,    g_dinv);
    cudaGetSymbolAddress((void**)&xh,      g_xh);
    cudaGetSymbolAddress((void**)&w1t,     g_w1t);
    cudaGetSymbolAddress((void**)&w2t,     g_w2t);
    cudaGetSymbolAddress((void**)&h1,      g_h1);
    cudaGetSymbolAddress((void**)&y1,      g_y1);
    cudaGetSymbolAddress((void**)&h2,      g_h2);
    cudaGetSymbolAddress((void**)&cnt,     g_cnt);
    cudaGetSymbolAddress((void**)&row_ptr, g_row_ptr);
    cudaGetSymbolAddress((void**)&fill,    g_fill);
    cudaGetSymbolAddress((void**)&col,     g_col);
    cudaGetSymbolAddress((void**)&state,   g_scanstate);

    static cudaStream_t s1 = nullptr;
    static cudaEvent_t evA = nullptr, evB = nullptr;
    if (s1 == nullptr) {
        cudaStreamCreateWithFlags(&s1, cudaStreamNonBlocking);
        cudaEventCreateWithFlags(&evA, cudaEventDisableTiming);
        cudaEventCreateWithFlags(&evB, cudaEventDisableTiming);
    }

    const int T = 256;

    // fork: CSR chain on s1, fp16 conversion + GEMM1 on main stream
    cudaEventRecord(evA, 0);
    cudaStreamWaitEvent(s1, evA, 0);

    cudaMemsetAsync(cnt,   0, N_NODES * sizeof(int), s1);
    cudaMemsetAsync(state, 0, SCAN_BLOCKS * sizeof(unsigned long long), s1);
    convert_edges_kernel<<<(2 * N_EDGES + T - 1) / T, T, 0, s1>>>(edge, cnt);
    scan_lookback_kernel<<<SCAN_BLOCKS, 1024, 0, s1>>>(cnt, row_ptr, dinv, fill, state);
    fill_csr_kernel<<<(N_EDGES + T - 1) / T, T, 0, s1>>>(fill, col, dinv);
    cudaEventRecord(evB, s1);

    // main: convert weights + x, then GEMM1
    convert_wt_kernel<<<DIM_HID, 256>>>(W1, w1t, DIM_IN, DIM_HID);
    convert_x_kernel<<<(N_NODES * DIM_IN / 8 + T - 1) / T, T>>>(x, xh, N_NODES * DIM_IN / 8);
    {
        dim3 grid(DIM_HID / BNH, (N_NODES + BMH - 1) / BMH);
        gemm_fp16_pipe<<<grid, 256>>>(xh, w1t, h1, N_NODES, DIM_IN, DIM_HID);
    }
    convert_wt_kernel<<<DIM_OUT, 256>>>(W2, w2t, DIM_HID, DIM_OUT);

    // join
    cudaStreamWaitEvent(0, evB, 0);

    gather_gate_kernel<DIM_HID, true, true><<<(N_NODES * 32 + T - 1) / T, T>>>(
        h1, row_ptr, col, dinv, b1, aw1, ab1, y1);

    {
        dim3 grid(DIM_OUT / BNH, (N_NODES + BMH - 1) / BMH);
        gemm_fp16_pipe<<<grid, 256>>>(y1, w2t, h2, N_NODES, DIM_HID, DIM_OUT);
    }

    gather_gate_kernel<DIM_OUT, false, false><<<(N_NODES * 32 + T - 1) / T, T>>>(
        h2, row_ptr, col, dinv, b2, aw2, ab2, out);
}